// round 3
// baseline (speedup 1.0000x reference)
#include <cuda_runtime.h>
#include <cstdint>

// Problem constants
#define Bb 64
#define Ii 2048
#define Oo 2048
#define Ss 10
#define Cc 512

// Main kernel tiling
#define TO 16               // o's per CTA
#define KC 16               // K (i) chunk
#define NC 12               // floats per (o,k) cell: 10 seg + 1 w + 1 pad
#define OSTR (KC*NC + 4)    // 196: per-o stride in ds (bank-skewed)
#define KSPLIT 4
#define KPER (Ii / KSPLIT)  // 512 i's per split
#define NCHUNK_S (KPER / KC) // 32 chunks
#define XSL 12              // x smem slot stride (floats), 16B-aligned, banks distinct
#define XKR (8 * XSL)       // 96 floats per k row

// -------- scratch (device globals) --------
__device__ float g_ctx_mean[Bb];
__device__ float g_mean_astro[Oo];
__device__ float g_sg[Oo * Ss];
__device__ float g_effw[(size_t)Oo * Ii];
// partial sums: [split][b][o][12] = 10 seg accs + w acc + pad
__device__ float g_part[(size_t)KSPLIT * Bb * Oo * 12];

// -------- helpers --------
__device__ __forceinline__ uint32_t sa(const void* p) {
    return (uint32_t)__cvta_generic_to_shared(p);
}
__device__ __forceinline__ void cpa8(uint32_t dst, const void* src) {
    asm volatile("cp.async.ca.shared.global [%0], [%1], 8;\n" :: "r"(dst), "l"(src));
}
__device__ __forceinline__ void cpa4(uint32_t dst, const void* src) {
    asm volatile("cp.async.ca.shared.global [%0], [%1], 4;\n" :: "r"(dst), "l"(src));
}
__device__ __forceinline__ void cpa_commit() {
    asm volatile("cp.async.commit_group;\n" ::: "memory");
}
__device__ __forceinline__ void cpa_wait1() {
    asm volatile("cp.async.wait_group 1;\n" ::: "memory");
}
__device__ __forceinline__ void cpa_wait0() {
    asm volatile("cp.async.wait_group 0;\n" ::: "memory");
}
__device__ __forceinline__ unsigned long long pk2(float x, float y) {
    unsigned long long r;
    asm("mov.b64 %0, {%1, %2};" : "=l"(r) : "f"(x), "f"(y));
    return r;
}
__device__ __forceinline__ void ffma2(unsigned long long& d, unsigned long long a, unsigned long long b) {
    asm("fma.rn.f32x2 %0, %1, %2, %0;" : "+l"(d) : "l"(a), "l"(b));
}
__device__ __forceinline__ void unpk2(unsigned long long v, float& a, float& b) {
    asm("mov.b64 {%0, %1}, %2;" : "=f"(a), "=f"(b) : "l"(v));
}
__device__ __forceinline__ float sigmoidf_(float z) {
    return 1.0f / (1.0f + expf(-z));
}

// -------- kernel 0: per-batch context mean --------
__global__ void k_ctx(const float* __restrict__ ctx) {
    int b = blockIdx.x;
    const float4* p = reinterpret_cast<const float4*>(ctx + (size_t)b * Cc);
    float4 v = p[threadIdx.x];
    float s = v.x + v.y + v.z + v.w;
    #pragma unroll
    for (int off = 16; off; off >>= 1) s += __shfl_down_sync(0xffffffffu, s, off);
    __shared__ float sm[4];
    if ((threadIdx.x & 31) == 0) sm[threadIdx.x >> 5] = s;
    __syncthreads();
    if (threadIdx.x == 0)
        g_ctx_mean[b] = (sm[0] + sm[1] + sm[2] + sm[3]) * (1.0f / Cc);
}

// -------- kernel 1: mean astro per o + sigmoid(gates) --------
__global__ void k_astro(const float* __restrict__ aact,
                        const float* __restrict__ athr,
                        const float* __restrict__ gates) {
    int o = blockIdx.x * blockDim.x + threadIdx.x;
    float act = aact[o];
    float thr = athr[o];
    float s = 0.0f;
    #pragma unroll 8
    for (int b = 0; b < Bb; b++) {
        float a = sigmoidf_(g_ctx_mean[b] * act);
        s += (a > thr) ? a : 0.0f;
    }
    g_mean_astro[o] = s * (1.0f / Bb);
    #pragma unroll
    for (int j = 0; j < Ss; j++)
        g_sg[o * Ss + j] = sigmoidf_(gates[o * Ss + j]);
}

// -------- kernel 2: pruned effective weight --------
__global__ void k_effw(const float* __restrict__ weight,
                       const float* __restrict__ cstr,
                       const float* __restrict__ pthr) {
    size_t i4 = (size_t)blockIdx.x * blockDim.x + threadIdx.x;
    float thr = pthr[0];
    float4 w = reinterpret_cast<const float4*>(weight)[i4];
    float4 c = reinterpret_cast<const float4*>(cstr)[i4];
    float4 r;
    r.x = (fabsf(w.x) * c.x > thr) ? w.x : 0.0f;
    r.y = (fabsf(w.y) * c.y > thr) ? w.y : 0.0f;
    r.z = (fabsf(w.z) * c.z > thr) ? w.z : 0.0f;
    r.w = (fabsf(w.w) * c.w > thr) ? w.w : 0.0f;
    reinterpret_cast<float4*>(g_effw)[i4] = r;
}

// -------- main GEMM-ish kernel: partial sums over a K split --------
// Grid (Oo/TO, KSPLIT). CTA: 128 threads = 16 oo x 8 slots. Each thread: one o,
// 8 batches (b = slot + 8j), 5 f32x2 segment accs + 1 w acc per batch.
__global__ void __launch_bounds__(128, 4)
k_main(const float* __restrict__ x,
       const float* __restrict__ dend,
       float* __restrict__ part) {
    __shared__ __align__(16) float ds[2][TO * OSTR];    // 25088 B
    __shared__ __align__(16) float xs[2][KC * XKR];     // 12288 B

    const int t = threadIdx.x;
    const int slot = t & 7;
    const int oo = t >> 3;
    const int oo_base = blockIdx.x * TO;
    const int split = blockIdx.y;
    const int kbase = split * KPER;

    // D loader: 2 cells per thread per chunk
    const int lk = t & 15;
    const int lo0 = t >> 4;          // 0..7
    const int lo1 = lo0 + 8;         // 8..15
    const float* dsrc0 = dend + ((size_t)(oo_base + lo0) * Ii + kbase + lk) * Ss;
    const float* dsrc1 = dend + ((size_t)(oo_base + lo1) * Ii + kbase + lk) * Ss;
    const float* wsrc0 = g_effw + (size_t)(oo_base + lo0) * Ii + kbase + lk;
    const float* wsrc1 = g_effw + (size_t)(oo_base + lo1) * Ii + kbase + lk;

    unsigned long long acc[8][5];
    float accw[8];
    #pragma unroll
    for (int j = 0; j < 8; j++) {
        accw[j] = 0.0f;
        #pragma unroll
        for (int p = 0; p < 5; p++) acc[j][p] = 0ull;
    }

    auto load_chunk = [&](int buf, int c) {
        const int coff = c * KC;
        // D cells
        {
            const float* s0 = dsrc0 + (size_t)coff * Ss;
            uint32_t d0 = sa(&ds[buf][lo0 * OSTR + lk * NC]);
            #pragma unroll
            for (int j = 0; j < 5; j++) cpa8(d0 + j * 8, s0 + j * 2);
            cpa4(d0 + 40, wsrc0 + coff);
            const float* s1 = dsrc1 + (size_t)coff * Ss;
            uint32_t d1 = sa(&ds[buf][lo1 * OSTR + lk * NC]);
            #pragma unroll
            for (int j = 0; j < 5; j++) cpa8(d1 + j * 8, s1 + j * 2);
            cpa4(d1 + 40, wsrc1 + coff);
        }
        // x: 1024 floats (64 b x 16 k) -> xs[k][slot][j], 8 cpa4 per thread
        #pragma unroll
        for (int r = 0; r < 8; r++) {
            int e = t + 128 * r;
            int b = e >> 4;
            int k = e & 15;
            cpa4(sa(&xs[buf][k * XKR + (b & 7) * XSL + (b >> 3)]),
                 x + (size_t)b * Ii + kbase + coff + k);
        }
    };

    load_chunk(0, 0);
    cpa_commit();

    int buf = 0;
    for (int c = 0; c < NCHUNK_S; c++) {
        if (c + 1 < NCHUNK_S) {
            load_chunk(buf ^ 1, c + 1);
            cpa_commit();
            cpa_wait1();
        } else {
            cpa_wait0();
        }
        __syncthreads();

        const float* dbase = &ds[buf][oo * OSTR];
        const float* xbase = &xs[buf][slot * XSL];
        #pragma unroll
        for (int k = 0; k < KC; k++) {
            const float* dr = dbase + k * NC;
            unsigned long long dp[5];
            #pragma unroll
            for (int p = 0; p < 5; p++)
                dp[p] = *reinterpret_cast<const unsigned long long*>(dr + 2 * p);
            float wv = dr[10];

            const float* xk = xbase + k * XKR;
            float4 xa = *reinterpret_cast<const float4*>(xk);
            float4 xb = *reinterpret_cast<const float4*>(xk + 4);
            float xv[8] = {xa.x, xa.y, xa.z, xa.w, xb.x, xb.y, xb.z, xb.w};
            #pragma unroll
            for (int j = 0; j < 8; j++) {
                unsigned long long xp = pk2(xv[j], xv[j]);
                #pragma unroll
                for (int p = 0; p < 5; p++) ffma2(acc[j][p], xp, dp[p]);
                accw[j] = fmaf(xv[j], wv, accw[j]);
            }
        }
        __syncthreads();
        buf ^= 1;
    }

    // write partials: [split][b][o][12]
    const int o = oo_base + oo;
    #pragma unroll
    for (int j = 0; j < 8; j++) {
        const int b = slot + 8 * j;
        float4* dst = reinterpret_cast<float4*>(
            part + (((size_t)split * Bb + b) * Oo + o) * 12);
        float s0, s1, s2, s3, s4, s5, s6, s7, s8, s9;
        unpk2(acc[j][0], s0, s1);
        unpk2(acc[j][1], s2, s3);
        unpk2(acc[j][2], s4, s5);
        unpk2(acc[j][3], s6, s7);
        unpk2(acc[j][4], s8, s9);
        dst[0] = make_float4(s0, s1, s2, s3);
        dst[1] = make_float4(s4, s5, s6, s7);
        dst[2] = make_float4(s8, s9, accw[j], 0.0f);
    }
}

// -------- final combine + nonlinearity --------
__global__ void k_fin(const float* __restrict__ bias, float* __restrict__ out) {
    int idx = blockIdx.x * blockDim.x + threadIdx.x;   // 131072 threads
    int b = idx >> 11;
    int o = idx & (Oo - 1);

    float seg[Ss];
    #pragma unroll
    for (int p = 0; p < Ss; p++) seg[p] = 0.0f;
    float w = 0.0f;

    #pragma unroll
    for (int s = 0; s < KSPLIT; s++) {
        const float4* src = reinterpret_cast<const float4*>(
            g_part + (((size_t)s * Bb + b) * Oo + o) * 12);
        float4 v0 = src[0], v1 = src[1], v2 = src[2];
        seg[0] += v0.x; seg[1] += v0.y; seg[2] += v0.z; seg[3] += v0.w;
        seg[4] += v1.x; seg[5] += v1.y; seg[6] += v1.z; seg[7] += v1.w;
        seg[8] += v2.x; seg[9] += v2.y; w += v2.z;
    }

    float v = fmaf(w, g_mean_astro[o], bias[o]);
    #pragma unroll
    for (int p = 0; p < Ss; p++)
        v = fmaf(g_sg[o * Ss + p], fmaxf(seg[p], 0.0f), v);
    out[(size_t)b * Oo + o] = fmaxf(v, 0.0f);
}

extern "C" void kernel_launch(void* const* d_in, const int* in_sizes, int n_in,
                              void* d_out, int out_size) {
    const float* x      = (const float*)d_in[0];
    const float* ctx    = (const float*)d_in[1];
    const float* weight = (const float*)d_in[3];
    const float* bias   = (const float*)d_in[4];
    const float* aact   = (const float*)d_in[5];
    const float* athr   = (const float*)d_in[6];
    const float* dend   = (const float*)d_in[7];
    const float* gates  = (const float*)d_in[8];
    const float* cstr   = (const float*)d_in[9];
    const float* pthr   = (const float*)d_in[10];
    float* out = (float*)d_out;

    float* part;
    cudaGetSymbolAddress((void**)&part, g_part);

    k_ctx<<<Bb, 128>>>(ctx);
    k_astro<<<Oo / 256, 256>>>(aact, athr, gates);
    k_effw<<<(Oo * (Ii / 4)) / 256, 256>>>(weight, cstr, pthr);
    k_main<<<dim3(Oo / TO, KSPLIT), 128>>>(x, dend, part);
    k_fin<<<(Bb * Oo) / 256, 256>>>(bias, out);
}

// round 4
// speedup vs baseline: 1.1444x; 1.1444x over previous
#include <cuda_runtime.h>
#include <cstdint>

// Problem constants
#define Bb 64
#define Ii 2048
#define Oo 2048
#define Ss 10
#define Cc 512

// Main kernel tiling
#define TO 16                 // o's per CTA
#define KC 16                 // K (i) chunk
#define NC 12                 // floats per (o,k) cell: 10 seg + 1 w + 1 pad (16B-multiple)
#define OSTR (KC*NC + 4)      // 196 floats: per-o stride in ds (16B-aligned, bank-skewed)
#define KSPLIT 2
#define KPER (Ii / KSPLIT)    // 1024 i's per split
#define NCHUNK_S (KPER / KC)  // 64 chunks
#define XKR 68                // x row stride (floats): 64 data + 4 pad, 16B-aligned

// -------- scratch (device globals) --------
__device__ float g_ctx_mean[Bb];
__device__ float g_mean_astro[Oo];
__device__ float g_sg[Oo * Ss];
__device__ float g_effw[(size_t)Oo * Ii];
// partial sums: [split][b][o][12] = 10 seg accs + w acc + pad
__device__ float g_part[(size_t)KSPLIT * Bb * Oo * 12];

// -------- helpers --------
__device__ __forceinline__ uint32_t sa(const void* p) {
    return (uint32_t)__cvta_generic_to_shared(p);
}
__device__ __forceinline__ void cpa8(uint32_t dst, const void* src) {
    asm volatile("cp.async.ca.shared.global [%0], [%1], 8;\n" :: "r"(dst), "l"(src));
}
__device__ __forceinline__ void cpa4(uint32_t dst, const void* src) {
    asm volatile("cp.async.ca.shared.global [%0], [%1], 4;\n" :: "r"(dst), "l"(src));
}
__device__ __forceinline__ void cpa_commit() {
    asm volatile("cp.async.commit_group;\n" ::: "memory");
}
__device__ __forceinline__ void cpa_wait1() {
    asm volatile("cp.async.wait_group 1;\n" ::: "memory");
}
__device__ __forceinline__ void cpa_wait0() {
    asm volatile("cp.async.wait_group 0;\n" ::: "memory");
}
__device__ __forceinline__ unsigned long long pk2(float x, float y) {
    unsigned long long r;
    asm("mov.b64 %0, {%1, %2};" : "=l"(r) : "f"(x), "f"(y));
    return r;
}
__device__ __forceinline__ void ffma2(unsigned long long& d, unsigned long long a, unsigned long long b) {
    asm("fma.rn.f32x2 %0, %1, %2, %0;" : "+l"(d) : "l"(a), "l"(b));
}
__device__ __forceinline__ void unpk2(unsigned long long v, float& a, float& b) {
    asm("mov.b64 {%0, %1}, %2;" : "=f"(a), "=f"(b) : "l"(v));
}
__device__ __forceinline__ unsigned long long f4lo(float4 v) { return pk2(v.x, v.y); }
__device__ __forceinline__ unsigned long long f4hi(float4 v) { return pk2(v.z, v.w); }
__device__ __forceinline__ float sigmoidf_(float z) {
    return 1.0f / (1.0f + expf(-z));
}

// -------- kernel 0: per-batch context mean --------
__global__ void k_ctx(const float* __restrict__ ctx) {
    int b = blockIdx.x;
    const float4* p = reinterpret_cast<const float4*>(ctx + (size_t)b * Cc);
    float4 v = p[threadIdx.x];
    float s = v.x + v.y + v.z + v.w;
    #pragma unroll
    for (int off = 16; off; off >>= 1) s += __shfl_down_sync(0xffffffffu, s, off);
    __shared__ float sm[4];
    if ((threadIdx.x & 31) == 0) sm[threadIdx.x >> 5] = s;
    __syncthreads();
    if (threadIdx.x == 0)
        g_ctx_mean[b] = (sm[0] + sm[1] + sm[2] + sm[3]) * (1.0f / Cc);
}

// -------- kernel 1: mean astro per o + sigmoid(gates) --------
__global__ void k_astro(const float* __restrict__ aact,
                        const float* __restrict__ athr,
                        const float* __restrict__ gates) {
    int o = blockIdx.x * blockDim.x + threadIdx.x;
    float act = aact[o];
    float thr = athr[o];
    float s = 0.0f;
    #pragma unroll 8
    for (int b = 0; b < Bb; b++) {
        float a = sigmoidf_(g_ctx_mean[b] * act);
        s += (a > thr) ? a : 0.0f;
    }
    g_mean_astro[o] = s * (1.0f / Bb);
    #pragma unroll
    for (int j = 0; j < Ss; j++)
        g_sg[o * Ss + j] = sigmoidf_(gates[o * Ss + j]);
}

// -------- kernel 2: pruned effective weight --------
__global__ void k_effw(const float* __restrict__ weight,
                       const float* __restrict__ cstr,
                       const float* __restrict__ pthr) {
    size_t i4 = (size_t)blockIdx.x * blockDim.x + threadIdx.x;
    float thr = pthr[0];
    float4 w = reinterpret_cast<const float4*>(weight)[i4];
    float4 c = reinterpret_cast<const float4*>(cstr)[i4];
    float4 r;
    r.x = (fabsf(w.x) * c.x > thr) ? w.x : 0.0f;
    r.y = (fabsf(w.y) * c.y > thr) ? w.y : 0.0f;
    r.z = (fabsf(w.z) * c.z > thr) ? w.z : 0.0f;
    r.w = (fabsf(w.w) * c.w > thr) ? w.w : 0.0f;
    reinterpret_cast<float4*>(g_effw)[i4] = r;
}

// -------- main kernel: partial sums over a K split --------
// Grid (Oo/TO, KSPLIT). CTA: 256 threads = 16 oo x 16 b0. Each thread: one o,
// 4 batches (b = b0 + 16j), 5 f32x2 segment accs + 1 w acc per batch.
// Per (thread, k): 3 LDS.128 (D cell) + 1 LDS.128 (4 x values) + 24 fma-class.
__global__ void __launch_bounds__(256, 2)
k_main(const float* __restrict__ x,
       const float* __restrict__ dend,
       float* __restrict__ part) {
    __shared__ __align__(16) float ds[2][TO * OSTR];  // 2 x 12544 B
    __shared__ __align__(16) float xs[2][KC * XKR];   // 2 x 4352 B

    const int t = threadIdx.x;
    const int b0 = t & 15;
    const int oo = t >> 4;
    const int oo_base = blockIdx.x * TO;
    const int split = blockIdx.y;
    const int kbase = split * KPER;

    // D loader: one (o,k) cell per thread per chunk
    const int lk = t & 15;
    const int lo = t >> 4;
    const float* dsrc = dend + ((size_t)(oo_base + lo) * Ii + kbase + lk) * Ss;
    const float* wsrc = g_effw + (size_t)(oo_base + lo) * Ii + kbase + lk;

    unsigned long long acc[4][5];
    float accw[4];
    #pragma unroll
    for (int j = 0; j < 4; j++) {
        accw[j] = 0.0f;
        #pragma unroll
        for (int p = 0; p < 5; p++) acc[j][p] = 0ull;
    }

    auto load_chunk = [&](int buf, int c) {
        const int coff = c * KC;
        // D cell: 10 segment floats (5x cpa8) + effective weight (cpa4 @ col 10)
        const float* s = dsrc + (size_t)coff * Ss;
        uint32_t d = sa(&ds[buf][lo * OSTR + lk * NC]);
        #pragma unroll
        for (int j = 0; j < 5; j++) cpa8(d + j * 8, s + j * 2);
        cpa4(d + 40, wsrc + coff);
        // x: 1024 floats (64 b x 16 k) -> xs[k][(b&15)*4 + (b>>4)]
        #pragma unroll
        for (int r = 0; r < 4; r++) {
            int e = t + 256 * r;
            int b = e >> 4;
            int k = e & 15;
            cpa4(sa(&xs[buf][k * XKR + ((b & 15) << 2) + (b >> 4)]),
                 x + (size_t)b * Ii + kbase + coff + k);
        }
    };

    load_chunk(0, 0);
    cpa_commit();

    int buf = 0;
    for (int c = 0; c < NCHUNK_S; c++) {
        if (c + 1 < NCHUNK_S) {
            load_chunk(buf ^ 1, c + 1);
            cpa_commit();
            cpa_wait1();
        } else {
            cpa_wait0();
        }
        __syncthreads();

        const float* dbase = &ds[buf][oo * OSTR];
        const float* xbase = &xs[buf][b0 << 2];
        #pragma unroll
        for (int k = 0; k < KC; k++) {
            const float* dr = dbase + k * NC;
            float4 v0 = *reinterpret_cast<const float4*>(dr);       // seg 0-3
            float4 v1 = *reinterpret_cast<const float4*>(dr + 4);   // seg 4-7
            float4 v2 = *reinterpret_cast<const float4*>(dr + 8);   // seg 8,9, w, pad
            unsigned long long dp[5] = {f4lo(v0), f4hi(v0), f4lo(v1), f4hi(v1), f4lo(v2)};
            float wv = v2.z;

            float4 xq = *reinterpret_cast<const float4*>(xbase + k * XKR);
            float xv[4] = {xq.x, xq.y, xq.z, xq.w};
            #pragma unroll
            for (int j = 0; j < 4; j++) {
                unsigned long long xp = pk2(xv[j], xv[j]);
                #pragma unroll
                for (int p = 0; p < 5; p++) ffma2(acc[j][p], xp, dp[p]);
                accw[j] = fmaf(xv[j], wv, accw[j]);
            }
        }
        __syncthreads();
        buf ^= 1;
    }

    // write partials: [split][b][o][12]
    const int o = oo_base + oo;
    #pragma unroll
    for (int j = 0; j < 4; j++) {
        const int b = b0 + 16 * j;
        float4* dst = reinterpret_cast<float4*>(
            part + (((size_t)split * Bb + b) * Oo + o) * 12);
        float s0, s1, s2, s3, s4, s5, s6, s7, s8, s9;
        unpk2(acc[j][0], s0, s1);
        unpk2(acc[j][1], s2, s3);
        unpk2(acc[j][2], s4, s5);
        unpk2(acc[j][3], s6, s7);
        unpk2(acc[j][4], s8, s9);
        dst[0] = make_float4(s0, s1, s2, s3);
        dst[1] = make_float4(s4, s5, s6, s7);
        dst[2] = make_float4(s8, s9, accw[j], 0.0f);
    }
}

// -------- final combine + nonlinearity --------
__global__ void k_fin(const float* __restrict__ bias, float* __restrict__ out) {
    int idx = blockIdx.x * blockDim.x + threadIdx.x;   // Bb*Oo threads
    int b = idx >> 11;
    int o = idx & (Oo - 1);

    float seg[Ss];
    #pragma unroll
    for (int p = 0; p < Ss; p++) seg[p] = 0.0f;
    float w = 0.0f;

    #pragma unroll
    for (int s = 0; s < KSPLIT; s++) {
        const float4* src = reinterpret_cast<const float4*>(
            g_part + (((size_t)s * Bb + b) * Oo + o) * 12);
        float4 v0 = src[0], v1 = src[1], v2 = src[2];
        seg[0] += v0.x; seg[1] += v0.y; seg[2] += v0.z; seg[3] += v0.w;
        seg[4] += v1.x; seg[5] += v1.y; seg[6] += v1.z; seg[7] += v1.w;
        seg[8] += v2.x; seg[9] += v2.y; w += v2.z;
    }

    float v = fmaf(w, g_mean_astro[o], bias[o]);
    #pragma unroll
    for (int p = 0; p < Ss; p++)
        v = fmaf(g_sg[o * Ss + p], fmaxf(seg[p], 0.0f), v);
    out[(size_t)b * Oo + o] = fmaxf(v, 0.0f);
}

extern "C" void kernel_launch(void* const* d_in, const int* in_sizes, int n_in,
                              void* d_out, int out_size) {
    const float* x      = (const float*)d_in[0];
    const float* ctx    = (const float*)d_in[1];
    const float* weight = (const float*)d_in[3];
    const float* bias   = (const float*)d_in[4];
    const float* aact   = (const float*)d_in[5];
    const float* athr   = (const float*)d_in[6];
    const float* dend   = (const float*)d_in[7];
    const float* gates  = (const float*)d_in[8];
    const float* cstr   = (const float*)d_in[9];
    const float* pthr   = (const float*)d_in[10];
    float* out = (float*)d_out;

    float* part;
    cudaGetSymbolAddress((void**)&part, g_part);

    k_ctx<<<Bb, 128>>>(ctx);
    k_astro<<<Oo / 256, 256>>>(aact, athr, gates);
    k_effw<<<(Oo * (Ii / 4)) / 256, 256>>>(weight, cstr, pthr);
    k_main<<<dim3(Oo / TO, KSPLIT), 256>>>(x, dend, part);
    k_fin<<<(Bb * Oo) / 256, 256>>>(bias, out);
}

// round 6
// speedup vs baseline: 1.7593x; 1.5374x over previous
#include <cuda_runtime.h>
#include <cstdint>

// Problem constants
#define Bb 64
#define Ii 2048
#define Oo 2048
#define Ss 10
#define Cc 512

// Tiling
#define No 16                 // o's per CTA -> N = 176 cols (11 per o)
#define KCH 64                // K chunk
#define NCHUNKS (Ii / KCH)    // 32

// smem layout (byte offsets from 1024-aligned base)
#define A_TILE 8192           // 64 rows x 128 B (bf16 [b][k] SW128)
#define B_TILE 22528          // 176 rows x 128 B (bf16 [n][k] SW128)
#define SM_A 0                // a_hi buf0, a_hi buf1, a_lo buf0, a_lo buf1
#define SM_B (4 * A_TILE)     // 32768: b_hi buf0, b_hi buf1, b_lo buf0, b_lo buf1
#define SM_EP SM_B            // epilogue fp32 [64][EPW] overlays B region
#define EPW 180
#define SMEM_REQ (SM_B + 4 * B_TILE + 1024)   // 123904

// -------- scratch globals --------
__device__ float g_ctx_mean[Bb];
__device__ float g_mean_astro[Oo];
__device__ uint32_t g_xhi[Bb * Ii / 2];   // bf16x2 [b][k]
__device__ uint32_t g_xlo[Bb * Ii / 2];

// -------- helpers --------
__device__ __forceinline__ uint32_t sa(const void* p) {
    return (uint32_t)__cvta_generic_to_shared(p);
}
__device__ __forceinline__ void cpa16(uint32_t dst, const void* src) {
    asm volatile("cp.async.cg.shared.global [%0], [%1], 16;\n" :: "r"(dst), "l"(src));
}
__device__ __forceinline__ void cpa_commit() {
    asm volatile("cp.async.commit_group;\n" ::: "memory");
}
__device__ __forceinline__ void cpa_waitg1() {
    asm volatile("cp.async.wait_group 1;\n" ::: "memory");
}
__device__ __forceinline__ void cpa_waitg0() {
    asm volatile("cp.async.wait_group 0;\n" ::: "memory");
}
__device__ __forceinline__ uint32_t cvt_bf16x2(float hi, float lo) {
    uint32_t r;
    asm("cvt.rn.bf16x2.f32 %0, %1, %2;" : "=r"(r) : "f"(hi), "f"(lo));
    return r;
}
__device__ __forceinline__ void sts64(uint32_t addr, uint32_t lo, uint32_t hi) {
    asm volatile("{\n\t.reg .b64 v;\n\tmov.b64 v, {%1, %2};\n\t"
                 "st.shared.b64 [%0], v;\n\t}" :: "r"(addr), "r"(lo), "r"(hi) : "memory");
}
__device__ __forceinline__ void stsv2(uint32_t addr, float x, float y) {
    asm volatile("st.shared.v2.f32 [%0], {%1, %2};" :: "r"(addr), "f"(x), "f"(y) : "memory");
}
__device__ __forceinline__ uint32_t swz(uint32_t off) {
    return off ^ ((off >> 3) & 0x70);
}
__device__ __forceinline__ float sigmoidf_(float z) {
    return 1.0f / (1.0f + __expf(-z));
}
__device__ __forceinline__ void ldsm4(uint32_t* r, uint32_t addr) {
    asm volatile("ldmatrix.sync.aligned.m8n8.x4.shared.b16 {%0,%1,%2,%3}, [%4];"
                 : "=r"(r[0]), "=r"(r[1]), "=r"(r[2]), "=r"(r[3]) : "r"(addr));
}
__device__ __forceinline__ void ldsm2(uint32_t* r, uint32_t addr) {
    asm volatile("ldmatrix.sync.aligned.m8n8.x2.shared.b16 {%0,%1}, [%2];"
                 : "=r"(r[0]), "=r"(r[1]) : "r"(addr));
}
__device__ __forceinline__ void hmma(float* c, const uint32_t* a, const uint32_t* b) {
    asm volatile(
        "mma.sync.aligned.m16n8k16.row.col.f32.bf16.bf16.f32 "
        "{%0,%1,%2,%3}, {%4,%5,%6,%7}, {%8,%9}, {%0,%1,%2,%3};"
        : "+f"(c[0]), "+f"(c[1]), "+f"(c[2]), "+f"(c[3])
        : "r"(a[0]), "r"(a[1]), "r"(a[2]), "r"(a[3]), "r"(b[0]), "r"(b[1]));
}

// -------- kernel 0: per-batch context mean --------
__global__ void k_ctx(const float* __restrict__ ctx) {
    int b = blockIdx.x;
    const float4* p = reinterpret_cast<const float4*>(ctx + (size_t)b * Cc);
    float4 v = p[threadIdx.x];
    float s = v.x + v.y + v.z + v.w;
    #pragma unroll
    for (int off = 16; off; off >>= 1) s += __shfl_down_sync(0xffffffffu, s, off);
    __shared__ float sm[4];
    if ((threadIdx.x & 31) == 0) sm[threadIdx.x >> 5] = s;
    __syncthreads();
    if (threadIdx.x == 0)
        g_ctx_mean[b] = (sm[0] + sm[1] + sm[2] + sm[3]) * (1.0f / Cc);
}

// -------- kernel 1: mean astro per o --------
__global__ void k_astro(const float* __restrict__ aact,
                        const float* __restrict__ athr) {
    int o = blockIdx.x * blockDim.x + threadIdx.x;
    float act = aact[o];
    float thr = athr[o];
    float s = 0.0f;
    #pragma unroll 8
    for (int b = 0; b < Bb; b++) {
        float a = 1.0f / (1.0f + expf(-g_ctx_mean[b] * act));
        s += (a > thr) ? a : 0.0f;
    }
    g_mean_astro[o] = s * (1.0f / Bb);
}

// -------- kernel 2: x -> bf16 hi/lo split --------
__global__ void k_xsplit(const float* __restrict__ x) {
    int e = blockIdx.x * blockDim.x + threadIdx.x;   // pair index
    float2 v = reinterpret_cast<const float2*>(x)[e];
    uint32_t h = cvt_bf16x2(v.y, v.x);               // lo half = v.x (k), hi = v.y (k+1)
    float g0 = __uint_as_float(h << 16);
    float g1 = __uint_as_float(h & 0xFFFF0000u);
    uint32_t l = cvt_bf16x2(v.y - g1, v.x - g0);
    g_xhi[e] = h;
    g_xlo[e] = l;
}

// -------- main tensor-core kernel (mma.sync bf16, 3-pass split) --------
// Grid 128, 256 threads (8 warps). Warp w: m-tile = 16*(w&3) (batches),
// n-half = 88*(w>>2); 11 m16n8 accumulator tiles per warp, registers.
__global__ void __launch_bounds__(256, 1)
k_main(const float* __restrict__ dend,
       const float* __restrict__ weight,
       const float* __restrict__ cstr,
       const float* __restrict__ pthr,
       const float* __restrict__ gates,
       const float* __restrict__ bias,
       float* __restrict__ out) {
    extern __shared__ char smraw[];
    uint32_t sb0 = sa(smraw);
    uint32_t sb = (sb0 + 1023u) & ~1023u;
    float* epf = reinterpret_cast<float*>(smraw + (sb - sb0) + SM_EP);

    const int t = threadIdx.x;
    const int lane = t & 31;
    const int w = t >> 5;
    const int wm = w & 3;
    const int wn = w >> 2;
    const int o_base = blockIdx.x * No;

    // converter mapping: o_loc = t>>4 (0..15), q = t&15 (k-quarter of the chunk)
    const int o_loc = t >> 4;
    const int q = t & 15;
    const int o = o_base + o_loc;
    const float thr = pthr[0];
    const int nrow = o_loc * 11;

    const uint32_t aHi0 = sb + SM_A;
    const uint32_t aLo0 = sb + SM_A + 2 * A_TILE;
    const uint32_t bHi0 = sb + SM_B;
    const uint32_t bLo0 = sb + SM_B + 2 * B_TILE;

    float acc[11][4];
    #pragma unroll
    for (int nt = 0; nt < 11; nt++) {
        acc[nt][0] = acc[nt][1] = acc[nt][2] = acc[nt][3] = 0.0f;
    }

    // registers holding the prefetched D/w/c for the next chunk
    float4 dreg[10];
    float4 w4, c4;

    auto prefetch = [&](int kb) {
        // 40 contiguous fp32: D[o][kb+4q .. +3][s=0..9]; index even -> 16B aligned
        const float4* dp4 = reinterpret_cast<const float4*>(
            dend + ((size_t)o * Ii + kb + 4 * q) * Ss);
        #pragma unroll
        for (int j = 0; j < 10; j++) dreg[j] = dp4[j];
        w4 = *reinterpret_cast<const float4*>(weight + (size_t)o * Ii + kb + 4 * q);
        c4 = *reinterpret_cast<const float4*>(cstr   + (size_t)o * Ii + kb + 4 * q);
    };

    auto convert_store = [&](int buf) {
        float f[40];
        #pragma unroll
        for (int j = 0; j < 10; j++) {
            f[4*j] = dreg[j].x; f[4*j+1] = dreg[j].y;
            f[4*j+2] = dreg[j].z; f[4*j+3] = dreg[j].w;
        }
        float wv[4];
        wv[0] = (fabsf(w4.x) * c4.x > thr) ? w4.x : 0.0f;
        wv[1] = (fabsf(w4.y) * c4.y > thr) ? w4.y : 0.0f;
        wv[2] = (fabsf(w4.z) * c4.z > thr) ? w4.z : 0.0f;
        wv[3] = (fabsf(w4.w) * c4.w > thr) ? w4.w : 0.0f;
        const uint32_t bhi = bHi0 + buf * B_TILE;
        const uint32_t blo = bLo0 + buf * B_TILE;
        #pragma unroll
        for (int s = 0; s < 11; s++) {
            float a0, a1, a2, a3;
            if (s < 10) { a0 = f[s]; a1 = f[10+s]; a2 = f[20+s]; a3 = f[30+s]; }
            else        { a0 = wv[0]; a1 = wv[1]; a2 = wv[2]; a3 = wv[3]; }
            uint32_t h0 = cvt_bf16x2(a1, a0);
            uint32_t h1 = cvt_bf16x2(a3, a2);
            float g0 = __uint_as_float(h0 << 16);
            float g1 = __uint_as_float(h0 & 0xFFFF0000u);
            float g2 = __uint_as_float(h1 << 16);
            float g3 = __uint_as_float(h1 & 0xFFFF0000u);
            uint32_t l0 = cvt_bf16x2(a1 - g1, a0 - g0);
            uint32_t l1 = cvt_bf16x2(a3 - g3, a2 - g2);
            uint32_t off = swz((uint32_t)(nrow + s) * 128 + q * 8);
            sts64(bhi + off, h0, h1);
            sts64(blo + off, l0, l1);
        }
    };

    auto loadA = [&](int buf, int kb) {
        #pragma unroll
        for (int r = 0; r < 4; r++) {
            int idx = t + 256 * r;           // 0..1023: 16B units of hi+lo A tiles
            int op = idx >> 9;
            int g = idx & 511;
            int b = g >> 3, sg_ = g & 7;
            const char* src = reinterpret_cast<const char*>(op ? g_xlo : g_xhi)
                            + ((size_t)b * Ii + kb + sg_ * 8) * 2;
            cpa16((op ? aLo0 : aHi0) + buf * A_TILE + swz((uint32_t)b * 128 + sg_ * 16), src);
        }
    };

    // lane-constant fragment address pieces (bytes, pre-swizzle)
    const uint32_t arow = (uint32_t)((wm * 16 + (lane & 15)) * 128 + (lane >> 4) * 16);
    const uint32_t brow = (uint32_t)((wn * 88 + (lane & 7)) * 128 + ((lane >> 3) & 1) * 16);

    // prologue: chunk 0
    prefetch(0);
    loadA(0, 0);
    cpa_commit();
    convert_store(0);

    for (int c = 0; c < NCHUNKS; c++) {
        const int buf = c & 1;
        if (c + 1 < NCHUNKS) {
            prefetch((c + 1) * KCH);      // LDG in flight across the MMA below
            loadA(buf ^ 1, (c + 1) * KCH);
            cpa_commit();
            cpa_waitg1();                  // chunk c's A complete
        } else {
            cpa_waitg0();
        }
        __syncthreads();                   // buf (A + B) visible to all warps

        const uint32_t ah_base = aHi0 + buf * A_TILE;
        const uint32_t al_base = aLo0 + buf * A_TILE;
        const uint32_t bh_base = bHi0 + buf * B_TILE;
        const uint32_t bl_base = bLo0 + buf * B_TILE;
        #pragma unroll
        for (int ks = 0; ks < 4; ks++) {
            uint32_t asw = swz(arow + ks * 32);
            uint32_t ah[4], al[4];
            ldsm4(ah, ah_base + asw);
            ldsm4(al, al_base + asw);
            #pragma unroll
            for (int nt = 0; nt < 11; nt++) {
                uint32_t offsw = swz(brow + (uint32_t)nt * 1024 + ks * 32);
                uint32_t bh[2], bl[2];
                ldsm2(bh, bh_base + offsw);
                ldsm2(bl, bl_base + offsw);
                hmma(acc[nt], ah, bh);     // x_hi * D_hi
                hmma(acc[nt], ah, bl);     // x_hi * D_lo
                hmma(acc[nt], al, bh);     // x_lo * D_hi
            }
        }
        if (c + 1 < NCHUNKS)
            convert_store(buf ^ 1);        // consume prefetched regs -> B smem
        __syncthreads();                   // all MMA reads of buf done before reuse
    }

    // ---- epilogue: dump accumulators to smem (overlays B region) ----
    #pragma unroll
    for (int nt = 0; nt < 11; nt++) {
        int row = wm * 16 + (lane >> 2);
        int col = wn * 88 + nt * 8 + 2 * (lane & 3);
        stsv2(sb + SM_EP + (uint32_t)((row * EPW + col) * 4), acc[nt][0], acc[nt][1]);
        stsv2(sb + SM_EP + (uint32_t)(((row + 8) * EPW + col) * 4), acc[nt][2], acc[nt][3]);
    }
    __syncthreads();

    // ---- phase 2: combine + nonlinearity, coalesced stores ----
    {
        const int ol = t & 15;
        const int bg = t >> 4;
        const int oo = o_base + ol;
        const float ma = g_mean_astro[oo];
        const float bv = bias[oo];
        float sg[Ss];
        #pragma unroll
        for (int s = 0; s < Ss; s++) sg[s] = sigmoidf_(gates[oo * Ss + s]);
        #pragma unroll
        for (int j = 0; j < 4; j++) {
            int b = bg * 4 + j;
            const float* e = epf + b * EPW + ol * 11;
            float v = fmaf(e[10], ma, bv);
            #pragma unroll
            for (int s = 0; s < Ss; s++)
                v = fmaf(sg[s], fmaxf(e[s], 0.0f), v);
            out[(size_t)b * Oo + oo] = fmaxf(v, 0.0f);
        }
    }
}

extern "C" void kernel_launch(void* const* d_in, const int* in_sizes, int n_in,
                              void* d_out, int out_size) {
    const float* x      = (const float*)d_in[0];
    const float* ctx    = (const float*)d_in[1];
    const float* weight = (const float*)d_in[3];
    const float* bias   = (const float*)d_in[4];
    const float* aact   = (const float*)d_in[5];
    const float* athr   = (const float*)d_in[6];
    const float* dend   = (const float*)d_in[7];
    const float* gates  = (const float*)d_in[8];
    const float* cstr   = (const float*)d_in[9];
    const float* pthr   = (const float*)d_in[10];
    float* out = (float*)d_out;

    cudaFuncSetAttribute(k_main, cudaFuncAttributeMaxDynamicSharedMemorySize, SMEM_REQ);

    k_ctx<<<Bb, 128>>>(ctx);
    k_astro<<<Oo / 256, 256>>>(aact, athr);
    k_xsplit<<<(Bb * Ii / 2) / 256, 256>>>(x);
    k_main<<<Oo / No, 256, SMEM_REQ>>>(dend, weight, cstr, pthr, gates, bias, out);
}

// round 7
// speedup vs baseline: 1.8428x; 1.0475x over previous
#include <cuda_runtime.h>
#include <cstdint>

// Problem constants
#define Bb 64
#define Ii 2048
#define Oo 2048
#define Ss 10
#define Cc 512

// Tiling
#define No 16                 // o's per CTA -> N = 176 cols (11 per o)
#define KCH 64                // K chunk
#define NCHUNKS (Ii / KCH)    // 32

// smem layout (byte offsets from 1024-aligned base)
#define A_TILE 8192           // 64 rows x 128 B (bf16 [b][k] SW128)
#define B_TILE 22528          // 176 rows x 128 B (bf16 [n][k] SW128)
#define SM_BAR 0              // mbarriers: full0@0 full1@8 empty0@16 empty1@24
#define SM_A 1024             // a_hi b0, a_hi b1, a_lo b0, a_lo b1
#define SM_B (SM_A + 4 * A_TILE)       // 33792: b_hi b0, b_hi b1, b_lo b0, b_lo b1
#define SM_EP SM_B            // epilogue fp32 [64][EPW] overlays B region
#define EPW 180
#define SMEM_REQ (SM_B + 4 * B_TILE + 1024)   // 124928

#define NTHREADS 384          // warps 0-7 consumers (MMA), 8-11 producers

// -------- scratch globals --------
__device__ float g_ctx_mean[Bb];
__device__ float g_mean_astro[Oo];
__device__ uint32_t g_xhi[Bb * Ii / 2];   // bf16x2 [b][k]
__device__ uint32_t g_xlo[Bb * Ii / 2];

// -------- helpers --------
__device__ __forceinline__ uint32_t sa(const void* p) {
    return (uint32_t)__cvta_generic_to_shared(p);
}
__device__ __forceinline__ void cpa16(uint32_t dst, const void* src) {
    asm volatile("cp.async.cg.shared.global [%0], [%1], 16;\n" :: "r"(dst), "l"(src));
}
__device__ __forceinline__ void cpa_commit() {
    asm volatile("cp.async.commit_group;\n" ::: "memory");
}
__device__ __forceinline__ void cpa_waitg0() {
    asm volatile("cp.async.wait_group 0;\n" ::: "memory");
}
__device__ __forceinline__ uint32_t cvt_bf16x2(float hi, float lo) {
    uint32_t r;
    asm("cvt.rn.bf16x2.f32 %0, %1, %2;" : "=r"(r) : "f"(hi), "f"(lo));
    return r;
}
__device__ __forceinline__ void sts64(uint32_t addr, uint32_t lo, uint32_t hi) {
    asm volatile("{\n\t.reg .b64 v;\n\tmov.b64 v, {%1, %2};\n\t"
                 "st.shared.b64 [%0], v;\n\t}" :: "r"(addr), "r"(lo), "r"(hi) : "memory");
}
__device__ __forceinline__ void stsv2(uint32_t addr, float x, float y) {
    asm volatile("st.shared.v2.f32 [%0], {%1, %2};" :: "r"(addr), "f"(x), "f"(y) : "memory");
}
__device__ __forceinline__ uint32_t swz(uint32_t off) {
    return off ^ ((off >> 3) & 0x70);
}
__device__ __forceinline__ float sigmoidf_(float z) {
    return 1.0f / (1.0f + __expf(-z));
}
__device__ __forceinline__ void ldsm4(uint32_t* r, uint32_t addr) {
    asm volatile("ldmatrix.sync.aligned.m8n8.x4.shared.b16 {%0,%1,%2,%3}, [%4];"
                 : "=r"(r[0]), "=r"(r[1]), "=r"(r[2]), "=r"(r[3]) : "r"(addr));
}
__device__ __forceinline__ void hmma(float* c, const uint32_t* a, const uint32_t* b) {
    asm volatile(
        "mma.sync.aligned.m16n8k16.row.col.f32.bf16.bf16.f32 "
        "{%0,%1,%2,%3}, {%4,%5,%6,%7}, {%8,%9}, {%0,%1,%2,%3};"
        : "+f"(c[0]), "+f"(c[1]), "+f"(c[2]), "+f"(c[3])
        : "r"(a[0]), "r"(a[1]), "r"(a[2]), "r"(a[3]), "r"(b[0]), "r"(b[1]));
}
__device__ __forceinline__ void mbar_init(uint32_t a, uint32_t cnt) {
    asm volatile("mbarrier.init.shared.b64 [%0], %1;" :: "r"(a), "r"(cnt) : "memory");
}
__device__ __forceinline__ void mbar_arrive(uint32_t a) {
    asm volatile("mbarrier.arrive.shared.b64 _, [%0];" :: "r"(a) : "memory");
}
__device__ __forceinline__ void mbar_wait(uint32_t a, uint32_t parity) {
    asm volatile(
        "{\n\t.reg .pred P1;\n\t"
        "WL_%=:\n\t"
        "mbarrier.try_wait.parity.acquire.cta.shared::cta.b64 P1, [%0], %1, 0x989680;\n\t"
        "@P1 bra.uni WD_%=;\n\t"
        "bra.uni WL_%=;\n\t"
        "WD_%=:\n\t}"
        :: "r"(a), "r"(parity) : "memory");
}
__device__ __forceinline__ void barsync(int id, int cnt) {
    asm volatile("bar.sync %0, %1;" :: "r"(id), "r"(cnt) : "memory");
}

// -------- kernel 0: per-batch context mean --------
__global__ void k_ctx(const float* __restrict__ ctx) {
    int b = blockIdx.x;
    const float4* p = reinterpret_cast<const float4*>(ctx + (size_t)b * Cc);
    float4 v = p[threadIdx.x];
    float s = v.x + v.y + v.z + v.w;
    #pragma unroll
    for (int off = 16; off; off >>= 1) s += __shfl_down_sync(0xffffffffu, s, off);
    __shared__ float sm[4];
    if ((threadIdx.x & 31) == 0) sm[threadIdx.x >> 5] = s;
    __syncthreads();
    if (threadIdx.x == 0)
        g_ctx_mean[b] = (sm[0] + sm[1] + sm[2] + sm[3]) * (1.0f / Cc);
}

// -------- kernel 1: mean astro per o --------
__global__ void k_astro(const float* __restrict__ aact,
                        const float* __restrict__ athr) {
    int o = blockIdx.x * blockDim.x + threadIdx.x;
    float act = aact[o];
    float thr = athr[o];
    float s = 0.0f;
    #pragma unroll 8
    for (int b = 0; b < Bb; b++) {
        float a = 1.0f / (1.0f + expf(-g_ctx_mean[b] * act));
        s += (a > thr) ? a : 0.0f;
    }
    g_mean_astro[o] = s * (1.0f / Bb);
}

// -------- kernel 2: x -> bf16 hi/lo split --------
__global__ void k_xsplit(const float* __restrict__ x) {
    int e = blockIdx.x * blockDim.x + threadIdx.x;
    float2 v = reinterpret_cast<const float2*>(x)[e];
    uint32_t h = cvt_bf16x2(v.y, v.x);
    float g0 = __uint_as_float(h << 16);
    float g1 = __uint_as_float(h & 0xFFFF0000u);
    uint32_t l = cvt_bf16x2(v.y - g1, v.x - g0);
    g_xhi[e] = h;
    g_xlo[e] = l;
}

// -------- main warp-specialized tensor kernel --------
// Grid 128, 384 threads. Warps 0-7: MMA consumers (wm = w&3 m-tile, wn = w>>2
// n-half, 11 m16n8 accum tiles). Warps 8-11: producers (LDG D/w/c, bf16 split,
// STS B tiles, cp.async A tiles). 2-stage ring with mbarrier full/empty pairs.
__global__ void __launch_bounds__(NTHREADS, 1)
k_main(const float* __restrict__ dend,
       const float* __restrict__ weight,
       const float* __restrict__ cstr,
       const float* __restrict__ pthr,
       const float* __restrict__ gates,
       const float* __restrict__ bias,
       float* __restrict__ out) {
    extern __shared__ char smraw[];
    uint32_t sb0 = sa(smraw);
    uint32_t sb = (sb0 + 1023u) & ~1023u;
    float* epf = reinterpret_cast<float*>(smraw + (sb - sb0) + SM_EP);

    const int t = threadIdx.x;
    const int o_base = blockIdx.x * No;

    const uint32_t FULL0 = sb + SM_BAR;
    const uint32_t EMPTY0 = sb + SM_BAR + 16;
    const uint32_t aHi0 = sb + SM_A;
    const uint32_t aLo0 = sb + SM_A + 2 * A_TILE;
    const uint32_t bHi0 = sb + SM_B;

    if (t == 0) {
        mbar_init(FULL0, 128);       // producers arrive
        mbar_init(FULL0 + 8, 128);
        mbar_init(EMPTY0, 256);      // consumers arrive
        mbar_init(EMPTY0 + 8, 256);
    }
    __syncthreads();

    if (t < 256) {
        // ================= CONSUMER =================
        const int lane = t & 31;
        const int w = t >> 5;
        const int wm = w & 3;
        const int wn = w >> 2;

        float acc[11][4];
        #pragma unroll
        for (int nt = 0; nt < 11; nt++)
            acc[nt][0] = acc[nt][1] = acc[nt][2] = acc[nt][3] = 0.0f;

        const uint32_t arow = (uint32_t)((wm * 16 + (lane & 15)) * 128 + (lane >> 4) * 16);
        // B ldsm4: lane groups 0,1 -> hi tile (koff 0,16B); groups 2,3 -> lo tile
        const int grp = lane >> 3;
        const uint32_t b_sel = (uint32_t)(grp >> 1) * (2 * B_TILE);
        const uint32_t brow = (uint32_t)((wn * 88 + (lane & 7)) * 128 + (grp & 1) * 16);

        int phf0 = 0, phf1 = 0;
        for (int c = 0; c < NCHUNKS; c++) {
            const int buf = c & 1;
            if (buf == 0) { mbar_wait(FULL0, phf0); phf0 ^= 1; }
            else          { mbar_wait(FULL0 + 8, phf1); phf1 ^= 1; }

            const uint32_t ah_base = aHi0 + buf * A_TILE;
            const uint32_t al_base = aLo0 + buf * A_TILE;
            const uint32_t bq_base = bHi0 + buf * B_TILE + b_sel;
            #pragma unroll
            for (int ks = 0; ks < 4; ks++) {
                uint32_t asw = swz(arow + ks * 32);
                uint32_t ah[4], al[4];
                ldsm4(ah, ah_base + asw);
                ldsm4(al, al_base + asw);
                #pragma unroll
                for (int nt = 0; nt < 11; nt++) {
                    uint32_t b4[4];
                    ldsm4(b4, bq_base + swz(brow + (uint32_t)nt * 1024 + ks * 32));
                    hmma(acc[nt], ah, b4);       // x_hi * D_hi
                    hmma(acc[nt], ah, b4 + 2);   // x_hi * D_lo
                    hmma(acc[nt], al, b4);       // x_lo * D_hi
                }
            }
            mbar_arrive(EMPTY0 + 8 * buf);
        }

        // ---- epilogue (consumers only) ----
        barsync(5, 256);                 // all consumer MMA reads of B done
        #pragma unroll
        for (int nt = 0; nt < 11; nt++) {
            int row = wm * 16 + (lane >> 2);
            int col = wn * 88 + nt * 8 + 2 * (lane & 3);
            stsv2(sb + SM_EP + (uint32_t)((row * EPW + col) * 4), acc[nt][0], acc[nt][1]);
            stsv2(sb + SM_EP + (uint32_t)(((row + 8) * EPW + col) * 4), acc[nt][2], acc[nt][3]);
        }
        barsync(5, 256);

        {
            const int ol = t & 15;
            const int bg = t >> 4;
            const int oo = o_base + ol;
            const float ma = g_mean_astro[oo];
            const float bv = bias[oo];
            float sg[Ss];
            #pragma unroll
            for (int s = 0; s < Ss; s++) sg[s] = sigmoidf_(gates[oo * Ss + s]);
            #pragma unroll
            for (int j = 0; j < 4; j++) {
                int b = bg * 4 + j;
                const float* e = epf + b * EPW + ol * 11;
                float v = fmaf(e[10], ma, bv);
                #pragma unroll
                for (int s = 0; s < Ss; s++)
                    v = fmaf(sg[s], fmaxf(e[s], 0.0f), v);
                out[(size_t)b * Oo + oo] = fmaxf(v, 0.0f);
            }
        }
    } else {
        // ================= PRODUCER =================
        const int p = t - 256;           // 0..127
        const int o_loc = p >> 3;        // 0..15
        const int qp = p & 7;            // handles q = 2qp, 2qp+1 (k = 4q..4q+3)
        const int o = o_base + o_loc;
        const int nrow = o_loc * 11;
        const float thr = pthr[0];

        int phe0 = 0, phe1 = 0;
        for (int c = 0; c < NCHUNKS; c++) {
            const int buf = c & 1;
            const int kb = c * KCH;
            if (c >= 2) {
                if (buf == 0) { mbar_wait(EMPTY0, phe0); phe0 ^= 1; }
                else          { mbar_wait(EMPTY0 + 8, phe1); phe1 ^= 1; }
            }

            // A tiles: 1024 x 16B over 128 threads
            #pragma unroll
            for (int r = 0; r < 8; r++) {
                int idx = p + 128 * r;
                int op = idx >> 9;
                int g = idx & 511;
                int b = g >> 3, sg_ = g & 7;
                const char* src = reinterpret_cast<const char*>(op ? g_xlo : g_xhi)
                                + ((size_t)b * Ii + kb + sg_ * 8) * 2;
                cpa16((op ? aLo0 : aHi0) + buf * A_TILE + swz((uint32_t)b * 128 + sg_ * 16), src);
            }
            cpa_commit();

            // prefetch both k-sub-blocks, then convert
            const int q0 = qp * 2, q1 = q0 + 1;
            float4 dA[10], dB[10];
            const float4* pA = reinterpret_cast<const float4*>(
                dend + ((size_t)o * Ii + kb + 4 * q0) * Ss);
            const float4* pB = reinterpret_cast<const float4*>(
                dend + ((size_t)o * Ii + kb + 4 * q1) * Ss);
            #pragma unroll
            for (int j = 0; j < 10; j++) dA[j] = pA[j];
            #pragma unroll
            for (int j = 0; j < 10; j++) dB[j] = pB[j];
            float4 wA = *reinterpret_cast<const float4*>(weight + (size_t)o * Ii + kb + 4 * q0);
            float4 cA = *reinterpret_cast<const float4*>(cstr   + (size_t)o * Ii + kb + 4 * q0);
            float4 wB = *reinterpret_cast<const float4*>(weight + (size_t)o * Ii + kb + 4 * q1);
            float4 cB = *reinterpret_cast<const float4*>(cstr   + (size_t)o * Ii + kb + 4 * q1);

            const uint32_t bhi = bHi0 + buf * B_TILE;
            const uint32_t blo = bhi + 2 * B_TILE;
            #pragma unroll
            for (int half = 0; half < 2; half++) {
                const float4* dr = half ? dB : dA;
                float4 w4 = half ? wB : wA;
                float4 c4 = half ? cB : cA;
                const int q = half ? q1 : q0;
                float f[40];
                #pragma unroll
                for (int j = 0; j < 10; j++) {
                    f[4*j] = dr[j].x; f[4*j+1] = dr[j].y;
                    f[4*j+2] = dr[j].z; f[4*j+3] = dr[j].w;
                }
                float wv[4];
                wv[0] = (fabsf(w4.x) * c4.x > thr) ? w4.x : 0.0f;
                wv[1] = (fabsf(w4.y) * c4.y > thr) ? w4.y : 0.0f;
                wv[2] = (fabsf(w4.z) * c4.z > thr) ? w4.z : 0.0f;
                wv[3] = (fabsf(w4.w) * c4.w > thr) ? w4.w : 0.0f;
                #pragma unroll
                for (int s = 0; s < 11; s++) {
                    float a0, a1, a2, a3;
                    if (s < 10) { a0 = f[s]; a1 = f[10+s]; a2 = f[20+s]; a3 = f[30+s]; }
                    else        { a0 = wv[0]; a1 = wv[1]; a2 = wv[2]; a3 = wv[3]; }
                    uint32_t h0 = cvt_bf16x2(a1, a0);
                    uint32_t h1 = cvt_bf16x2(a3, a2);
                    float g0 = __uint_as_float(h0 << 16);
                    float g1 = __uint_as_float(h0 & 0xFFFF0000u);
                    float g2 = __uint_as_float(h1 << 16);
                    float g3 = __uint_as_float(h1 & 0xFFFF0000u);
                    uint32_t l0 = cvt_bf16x2(a1 - g1, a0 - g0);
                    uint32_t l1 = cvt_bf16x2(a3 - g3, a2 - g2);
                    uint32_t off = swz((uint32_t)(nrow + s) * 128 + q * 8);
                    sts64(bhi + off, h0, h1);
                    sts64(blo + off, l0, l1);
                }
            }
            cpa_waitg0();                     // A tiles landed
            mbar_arrive(FULL0 + 8 * buf);     // release: STS + cp.async visible
        }
    }
}

extern "C" void kernel_launch(void* const* d_in, const int* in_sizes, int n_in,
                              void* d_out, int out_size) {
    const float* x      = (const float*)d_in[0];
    const float* ctx    = (const float*)d_in[1];
    const float* weight = (const float*)d_in[3];
    const float* bias   = (const float*)d_in[4];
    const float* aact   = (const float*)d_in[5];
    const float* athr   = (const float*)d_in[6];
    const float* dend   = (const float*)d_in[7];
    const float* gates  = (const float*)d_in[8];
    const float* cstr   = (const float*)d_in[9];
    const float* pthr   = (const float*)d_in[10];
    float* out = (float*)d_out;

    cudaFuncSetAttribute(k_main, cudaFuncAttributeMaxDynamicSharedMemorySize, SMEM_REQ);

    k_ctx<<<Bb, 128>>>(ctx);
    k_astro<<<Oo / 256, 256>>>(aact, athr);
    k_xsplit<<<(Bb * Ii / 2) / 256, 256>>>(x);
    k_main<<<Oo / No, NTHREADS, SMEM_REQ>>>(dend, weight, cstr, pthr, gates, bias, out);
}

// round 8
// speedup vs baseline: 2.3683x; 1.2852x over previous
#include <cuda_runtime.h>
#include <cuda_fp16.h>
#include <cstdint>

// Problem constants
#define Bb 64
#define Ii 2048
#define Oo 2048
#define Ss 10
#define Cc 512

// Tiling
#define No 16                 // o's per CTA
#define NCOL 12               // cols per o: 10 seg + w + pad
#define NN (No * NCOL)        // 192 MMA N columns
#define KCH 64                // K chunk
#define NCHUNKS (Ii / KCH)    // 32

// smem layout (byte offsets from 1024-aligned base)
#define A_TILE 8192           // 64 rows x 128 B (fp16 [b][k] SW128)
#define B_TILE 24576          // 192 rows x 128 B (fp16 [n][k] SW128)
#define SM_BAR 0              // full0@0 full1@8 empty0@16 empty1@24
#define SM_A 1024             // a_hi b0, a_hi b1, a_lo b0, a_lo b1
#define SM_B (SM_A + 4 * A_TILE)       // 33792: b tile buf0, buf1
#define SM_EP SM_A            // epilogue fp32 [64][EPW] overlays A+B region
#define EPW 196
#define SMEM_REQ (SM_B + 2 * B_TILE + 1024)   // 83968

#define NTHREADS 384          // warps 0-7 consumers (MMA), 8-11 producers

// -------- scratch globals --------
__device__ float g_ctx_mean[Bb];
__device__ float g_mean_astro[Oo];
__device__ uint32_t g_xhi[Bb * Ii / 2];   // fp16x2 [b][k]
__device__ uint32_t g_xlo[Bb * Ii / 2];

// -------- helpers --------
__device__ __forceinline__ uint32_t sa(const void* p) {
    return (uint32_t)__cvta_generic_to_shared(p);
}
__device__ __forceinline__ void cpa16(uint32_t dst, const void* src) {
    asm volatile("cp.async.cg.shared.global [%0], [%1], 16;\n" :: "r"(dst), "l"(src));
}
__device__ __forceinline__ void cpa_commit() {
    asm volatile("cp.async.commit_group;\n" ::: "memory");
}
__device__ __forceinline__ void cpa_waitg0() {
    asm volatile("cp.async.wait_group 0;\n" ::: "memory");
}
__device__ __forceinline__ uint32_t cvt_f16x2(float hi, float lo) {
    uint32_t r;
    asm("cvt.rn.f16x2.f32 %0, %1, %2;" : "=r"(r) : "f"(hi), "f"(lo));
    return r;
}
__device__ __forceinline__ void sts64(uint32_t addr, uint32_t lo, uint32_t hi) {
    asm volatile("{\n\t.reg .b64 v;\n\tmov.b64 v, {%1, %2};\n\t"
                 "st.shared.b64 [%0], v;\n\t}" :: "r"(addr), "r"(lo), "r"(hi) : "memory");
}
__device__ __forceinline__ void stsv2(uint32_t addr, float x, float y) {
    asm volatile("st.shared.v2.f32 [%0], {%1, %2};" :: "r"(addr), "f"(x), "f"(y) : "memory");
}
__device__ __forceinline__ void stsz16(uint32_t addr) {
    asm volatile("st.shared.v4.b32 [%0], {%1, %1, %1, %1};" :: "r"(addr), "r"(0u) : "memory");
}
__device__ __forceinline__ uint32_t swz(uint32_t off) {
    return off ^ ((off >> 3) & 0x70);
}
__device__ __forceinline__ float sigmoidf_(float z) {
    return 1.0f / (1.0f + __expf(-z));
}
__device__ __forceinline__ void ldsm4(uint32_t* r, uint32_t addr) {
    asm volatile("ldmatrix.sync.aligned.m8n8.x4.shared.b16 {%0,%1,%2,%3}, [%4];"
                 : "=r"(r[0]), "=r"(r[1]), "=r"(r[2]), "=r"(r[3]) : "r"(addr));
}
__device__ __forceinline__ void hmma(float* c, const uint32_t* a, const uint32_t* b) {
    asm volatile(
        "mma.sync.aligned.m16n8k16.row.col.f32.f16.f16.f32 "
        "{%0,%1,%2,%3}, {%4,%5,%6,%7}, {%8,%9}, {%0,%1,%2,%3};"
        : "+f"(c[0]), "+f"(c[1]), "+f"(c[2]), "+f"(c[3])
        : "r"(a[0]), "r"(a[1]), "r"(a[2]), "r"(a[3]), "r"(b[0]), "r"(b[1]));
}
__device__ __forceinline__ void mbar_init(uint32_t a, uint32_t cnt) {
    asm volatile("mbarrier.init.shared.b64 [%0], %1;" :: "r"(a), "r"(cnt) : "memory");
}
__device__ __forceinline__ void mbar_arrive(uint32_t a) {
    asm volatile("mbarrier.arrive.shared.b64 _, [%0];" :: "r"(a) : "memory");
}
__device__ __forceinline__ void mbar_wait(uint32_t a, uint32_t parity) {
    asm volatile(
        "{\n\t.reg .pred P1;\n\t"
        "WL_%=:\n\t"
        "mbarrier.try_wait.parity.acquire.cta.shared::cta.b64 P1, [%0], %1, 0x989680;\n\t"
        "@P1 bra.uni WD_%=;\n\t"
        "bra.uni WL_%=;\n\t"
        "WD_%=:\n\t}"
        :: "r"(a), "r"(parity) : "memory");
}
__device__ __forceinline__ void barsync(int id, int cnt) {
    asm volatile("bar.sync %0, %1;" :: "r"(id), "r"(cnt) : "memory");
}

// -------- kernel 0: per-batch context mean --------
__global__ void k_ctx(const float* __restrict__ ctx) {
    int b = blockIdx.x;
    const float4* p = reinterpret_cast<const float4*>(ctx + (size_t)b * Cc);
    float4 v = p[threadIdx.x];
    float s = v.x + v.y + v.z + v.w;
    #pragma unroll
    for (int off = 16; off; off >>= 1) s += __shfl_down_sync(0xffffffffu, s, off);
    __shared__ float sm[4];
    if ((threadIdx.x & 31) == 0) sm[threadIdx.x >> 5] = s;
    __syncthreads();
    if (threadIdx.x == 0)
        g_ctx_mean[b] = (sm[0] + sm[1] + sm[2] + sm[3]) * (1.0f / Cc);
}

// -------- kernel 1: mean astro per o --------
__global__ void k_astro(const float* __restrict__ aact,
                        const float* __restrict__ athr) {
    int o = blockIdx.x * blockDim.x + threadIdx.x;
    float act = aact[o];
    float thr = athr[o];
    float s = 0.0f;
    #pragma unroll 8
    for (int b = 0; b < Bb; b++) {
        float a = 1.0f / (1.0f + expf(-g_ctx_mean[b] * act));
        s += (a > thr) ? a : 0.0f;
    }
    g_mean_astro[o] = s * (1.0f / Bb);
}

// -------- kernel 2: x -> fp16 hi/lo split --------
__global__ void k_xsplit(const float* __restrict__ x) {
    int e = blockIdx.x * blockDim.x + threadIdx.x;
    float2 v = reinterpret_cast<const float2*>(x)[e];
    uint32_t h = cvt_f16x2(v.y, v.x);                 // lo half = v.x
    __half2 h2 = *reinterpret_cast<__half2*>(&h);
    float2 hf = __half22float2(h2);
    uint32_t l = cvt_f16x2(v.y - hf.y, v.x - hf.x);
    g_xhi[e] = h;
    g_xlo[e] = l;
}

// -------- main warp-specialized fp16 tensor kernel --------
// Grid 128, 384 threads. Consumers (warps 0-7): wm = w&1 (2 m16-tiles),
// wn = w>>1 (48 n-cols = 6 n8-tiles). Producers (warps 8-11): LDG D/w/c,
// fp16 convert, STS B tile; cp.async A tiles. Passes: x_hi*D + x_lo*D.
__global__ void __launch_bounds__(NTHREADS, 1)
k_main(const float* __restrict__ dend,
       const float* __restrict__ weight,
       const float* __restrict__ cstr,
       const float* __restrict__ pthr,
       const float* __restrict__ gates,
       const float* __restrict__ bias,
       float* __restrict__ out) {
    extern __shared__ char smraw[];
    uint32_t sb0 = sa(smraw);
    uint32_t sb = (sb0 + 1023u) & ~1023u;
    float* epf = reinterpret_cast<float*>(smraw + (sb - sb0) + SM_EP);

    const int t = threadIdx.x;
    const int o_base = blockIdx.x * No;

    const uint32_t FULL0 = sb + SM_BAR;
    const uint32_t EMPTY0 = sb + SM_BAR + 16;
    const uint32_t aHi0 = sb + SM_A;
    const uint32_t aLo0 = sb + SM_A + 2 * A_TILE;
    const uint32_t bT0 = sb + SM_B;

    if (t == 0) {
        mbar_init(FULL0, 128);
        mbar_init(FULL0 + 8, 128);
        mbar_init(EMPTY0, 256);
        mbar_init(EMPTY0 + 8, 256);
    }
    // zero the pad column rows (n % 12 == 11) of both B buffers, once
    if (t < 256) {
        int buf = t >> 7, ol = (t >> 3) & 15, seg = t & 7;
        uint32_t n = (uint32_t)(ol * NCOL + 11);
        stsz16(bT0 + buf * B_TILE + swz(n * 128 + seg * 16));
    }
    __syncthreads();

    if (t < 256) {
        // ================= CONSUMER =================
        const int lane = t & 31;
        const int w = t >> 5;
        const int wm = w & 1;
        const int wn = w >> 1;

        float acc[2][6][4];
        #pragma unroll
        for (int mt = 0; mt < 2; mt++)
            #pragma unroll
            for (int nt = 0; nt < 6; nt++)
                acc[mt][nt][0] = acc[mt][nt][1] = acc[mt][nt][2] = acc[mt][nt][3] = 0.0f;

        const int grp = lane >> 3;
        const uint32_t arow0 = (uint32_t)((wm * 32 + (lane & 15)) * 128 + (lane >> 4) * 16);
        const uint32_t arow1 = arow0 + 16 * 128;
        // B ldsm4 pairs adjacent n8-tiles: groups 0,1 -> rows +0 (k 0/16B),
        // groups 2,3 -> rows +8
        const uint32_t brow = (uint32_t)((wn * 48 + (grp >> 1) * 8 + (lane & 7)) * 128
                                         + (grp & 1) * 16);

        int phf0 = 0, phf1 = 0;
        for (int c = 0; c < NCHUNKS; c++) {
            const int buf = c & 1;
            if (buf == 0) { mbar_wait(FULL0, phf0); phf0 ^= 1; }
            else          { mbar_wait(FULL0 + 8, phf1); phf1 ^= 1; }

            const uint32_t ahb = aHi0 + buf * A_TILE;
            const uint32_t alb = aLo0 + buf * A_TILE;
            const uint32_t bb = bT0 + buf * B_TILE;
            #pragma unroll
            for (int ks = 0; ks < 4; ks++) {
                uint32_t ah0[4], al0[4], ah1[4], al1[4];
                uint32_t asw0 = swz(arow0 + ks * 32);
                uint32_t asw1 = swz(arow1 + ks * 32);
                ldsm4(ah0, ahb + asw0);
                ldsm4(al0, alb + asw0);
                ldsm4(ah1, ahb + asw1);
                ldsm4(al1, alb + asw1);
                #pragma unroll
                for (int pr = 0; pr < 3; pr++) {
                    uint32_t b4[4];
                    ldsm4(b4, bb + swz(brow + (uint32_t)pr * 2048 + ks * 32));
                    hmma(acc[0][2*pr],   ah0, b4);
                    hmma(acc[0][2*pr],   al0, b4);
                    hmma(acc[0][2*pr+1], ah0, b4 + 2);
                    hmma(acc[0][2*pr+1], al0, b4 + 2);
                    hmma(acc[1][2*pr],   ah1, b4);
                    hmma(acc[1][2*pr],   al1, b4);
                    hmma(acc[1][2*pr+1], ah1, b4 + 2);
                    hmma(acc[1][2*pr+1], al1, b4 + 2);
                }
            }
            mbar_arrive(EMPTY0 + 8 * buf);
        }

        // ---- epilogue ----
        barsync(5, 256);
        #pragma unroll
        for (int mt = 0; mt < 2; mt++) {
            int row = wm * 32 + mt * 16 + (lane >> 2);
            #pragma unroll
            for (int nt = 0; nt < 6; nt++) {
                int col = wn * 48 + nt * 8 + 2 * (lane & 3);
                stsv2(sb + SM_EP + (uint32_t)((row * EPW + col) * 4),
                      acc[mt][nt][0], acc[mt][nt][1]);
                stsv2(sb + SM_EP + (uint32_t)(((row + 8) * EPW + col) * 4),
                      acc[mt][nt][2], acc[mt][nt][3]);
            }
        }
        barsync(5, 256);

        {
            const int ol = t & 15;
            const int bg = t >> 4;
            const int oo = o_base + ol;
            const float ma = g_mean_astro[oo];
            const float bv = bias[oo];
            float sg[Ss];
            #pragma unroll
            for (int s = 0; s < Ss; s++) sg[s] = sigmoidf_(gates[oo * Ss + s]);
            #pragma unroll
            for (int j = 0; j < 4; j++) {
                int b = bg * 4 + j;
                const float* e = epf + b * EPW + ol * NCOL;
                float v = fmaf(e[10], ma, bv);
                #pragma unroll
                for (int s = 0; s < Ss; s++)
                    v = fmaf(sg[s], fmaxf(e[s], 0.0f), v);
                out[(size_t)b * Oo + oo] = fmaxf(v, 0.0f);
            }
        }
    } else {
        // ================= PRODUCER =================
        const int p = t - 256;
        const int o_loc = p >> 3;
        const int qp = p & 7;            // q = 2qp, 2qp+1 (k = 4q..4q+3)
        const int o = o_base + o_loc;
        const int nrow = o_loc * NCOL;
        const float thr = pthr[0];

        int phe0 = 0, phe1 = 0;
        for (int c = 0; c < NCHUNKS; c++) {
            const int buf = c & 1;
            const int kb = c * KCH;
            if (c >= 2) {
                if (buf == 0) { mbar_wait(EMPTY0, phe0); phe0 ^= 1; }
                else          { mbar_wait(EMPTY0 + 8, phe1); phe1 ^= 1; }
            }

            // A tiles: x_hi/x_lo fp16, 1024 x 16B over 128 threads
            #pragma unroll
            for (int r = 0; r < 8; r++) {
                int idx = p + 128 * r;
                int op = idx >> 9;
                int g = idx & 511;
                int b = g >> 3, sg_ = g & 7;
                const char* src = reinterpret_cast<const char*>(op ? g_xlo : g_xhi)
                                + ((size_t)b * Ii + kb + sg_ * 8) * 2;
                cpa16((op ? aLo0 : aHi0) + buf * A_TILE + swz((uint32_t)b * 128 + sg_ * 16), src);
            }
            cpa_commit();

            const int q0 = qp * 2, q1 = q0 + 1;
            float4 dA[10], dB[10];
            const float4* pA = reinterpret_cast<const float4*>(
                dend + ((size_t)o * Ii + kb + 4 * q0) * Ss);
            const float4* pB = reinterpret_cast<const float4*>(
                dend + ((size_t)o * Ii + kb + 4 * q1) * Ss);
            #pragma unroll
            for (int j = 0; j < 10; j++) dA[j] = pA[j];
            #pragma unroll
            for (int j = 0; j < 10; j++) dB[j] = pB[j];
            float4 wA = *reinterpret_cast<const float4*>(weight + (size_t)o * Ii + kb + 4 * q0);
            float4 cA = *reinterpret_cast<const float4*>(cstr   + (size_t)o * Ii + kb + 4 * q0);
            float4 wB = *reinterpret_cast<const float4*>(weight + (size_t)o * Ii + kb + 4 * q1);
            float4 cB = *reinterpret_cast<const float4*>(cstr   + (size_t)o * Ii + kb + 4 * q1);

            const uint32_t bb = bT0 + buf * B_TILE;
            #pragma unroll
            for (int half = 0; half < 2; half++) {
                const float4* dr = half ? dB : dA;
                float4 w4 = half ? wB : wA;
                float4 c4 = half ? cB : cA;
                const int q = half ? q1 : q0;
                float f[40];
                #pragma unroll
                for (int j = 0; j < 10; j++) {
                    f[4*j] = dr[j].x; f[4*j+1] = dr[j].y;
                    f[4*j+2] = dr[j].z; f[4*j+3] = dr[j].w;
                }
                float wv[4];
                wv[0] = (fabsf(w4.x) * c4.x > thr) ? w4.x : 0.0f;
                wv[1] = (fabsf(w4.y) * c4.y > thr) ? w4.y : 0.0f;
                wv[2] = (fabsf(w4.z) * c4.z > thr) ? w4.z : 0.0f;
                wv[3] = (fabsf(w4.w) * c4.w > thr) ? w4.w : 0.0f;
                #pragma unroll
                for (int s = 0; s < 11; s++) {
                    float a0, a1, a2, a3;
                    if (s < 10) { a0 = f[s]; a1 = f[10+s]; a2 = f[20+s]; a3 = f[30+s]; }
                    else        { a0 = wv[0]; a1 = wv[1]; a2 = wv[2]; a3 = wv[3]; }
                    uint32_t h0 = cvt_f16x2(a1, a0);
                    uint32_t h1 = cvt_f16x2(a3, a2);
                    sts64(bb + swz((uint32_t)(nrow + s) * 128 + q * 8), h0, h1);
                }
            }
            cpa_waitg0();
            mbar_arrive(FULL0 + 8 * buf);
        }
    }
}

extern "C" void kernel_launch(void* const* d_in, const int* in_sizes, int n_in,
                              void* d_out, int out_size) {
    const float* x      = (const float*)d_in[0];
    const float* ctx    = (const float*)d_in[1];
    const float* weight = (const float*)d_in[3];
    const float* bias   = (const float*)d_in[4];
    const float* aact   = (const float*)d_in[5];
    const float* athr   = (const float*)d_in[6];
    const float* dend   = (const float*)d_in[7];
    const float* gates  = (const float*)d_in[8];
    const float* cstr   = (const float*)d_in[9];
    const float* pthr   = (const float*)d_in[10];
    float* out = (float*)d_out;

    cudaFuncSetAttribute(k_main, cudaFuncAttributeMaxDynamicSharedMemorySize, SMEM_REQ);

    k_ctx<<<Bb, 128>>>(ctx);
    k_astro<<<Oo / 256, 256>>>(aact, athr);
    k_xsplit<<<(Bb * Ii / 2) / 256, 256>>>(x);
    k_main<<<Oo / No, NTHREADS, SMEM_REQ>>>(dend, weight, cstr, pthr, gates, bias, out);
}

// round 9
// speedup vs baseline: 2.4066x; 1.0162x over previous
#include <cuda_runtime.h>
#include <cuda_fp16.h>
#include <cstdint>

// Problem constants
#define Bb 64
#define Ii 2048
#define Oo 2048
#define Ss 10
#define Cc 512

// Tiling
#define No 16                 // o's per CTA
#define NCOL 12               // cols per o: 10 seg + w + pad
#define KCH 64                // K chunk
#define NCHUNKS (Ii / KCH)    // 32
#define STAGES 4

// smem layout (byte offsets from 1024-aligned base)
#define A_TILE 8192           // 64 rows x 128 B (fp16 [b][k] SW128)
#define B_TILE 24576          // 192 rows x 128 B (fp16 [n][k] SW128)
#define SM_BAR 0              // full[st]@st*8, empty[st]@32+st*8
#define SM_A 1024             // aHi[0..3], aLo[0..3]
#define SM_B (SM_A + 8 * A_TILE)           // 66560
#define SM_EP SM_A            // epilogue fp32 [64][EPW] overlays A region
#define EPW 196
#define SMEM_REQ (SM_B + STAGES * B_TILE + 1024)   // 165888

#define NTHREADS 384          // warps 0-7 consumers (MMA), 8-11 producers

// -------- scratch globals --------
__device__ float g_ctx_mean[Bb];
__device__ float g_mean_astro[Oo];
__device__ uint32_t g_xhi[Bb * Ii / 2];   // fp16x2 [b][k]
__device__ uint32_t g_xlo[Bb * Ii / 2];

// -------- helpers --------
__device__ __forceinline__ uint32_t sa(const void* p) {
    return (uint32_t)__cvta_generic_to_shared(p);
}
__device__ __forceinline__ void cpa16(uint32_t dst, const void* src) {
    asm volatile("cp.async.cg.shared.global [%0], [%1], 16;\n" :: "r"(dst), "l"(src));
}
__device__ __forceinline__ void cpa_commit() {
    asm volatile("cp.async.commit_group;\n" ::: "memory");
}
__device__ __forceinline__ void cpa_waitg0() {
    asm volatile("cp.async.wait_group 0;\n" ::: "memory");
}
__device__ __forceinline__ uint32_t cvt_f16x2(float hi, float lo) {
    uint32_t r;
    asm("cvt.rn.f16x2.f32 %0, %1, %2;" : "=r"(r) : "f"(hi), "f"(lo));
    return r;
}
__device__ __forceinline__ void sts64(uint32_t addr, uint32_t lo, uint32_t hi) {
    asm volatile("{\n\t.reg .b64 v;\n\tmov.b64 v, {%1, %2};\n\t"
                 "st.shared.b64 [%0], v;\n\t}" :: "r"(addr), "r"(lo), "r"(hi) : "memory");
}
__device__ __forceinline__ void stsv2(uint32_t addr, float x, float y) {
    asm volatile("st.shared.v2.f32 [%0], {%1, %2};" :: "r"(addr), "f"(x), "f"(y) : "memory");
}
__device__ __forceinline__ void stsz16(uint32_t addr) {
    asm volatile("st.shared.v4.b32 [%0], {%1, %1, %1, %1};" :: "r"(addr), "r"(0u) : "memory");
}
__device__ __forceinline__ uint32_t swz(uint32_t off) {
    return off ^ ((off >> 3) & 0x70);
}
__device__ __forceinline__ float sigmoidf_(float z) {
    return 1.0f / (1.0f + __expf(-z));
}
__device__ __forceinline__ void ldsm4(uint32_t* r, uint32_t addr) {
    asm volatile("ldmatrix.sync.aligned.m8n8.x4.shared.b16 {%0,%1,%2,%3}, [%4];"
                 : "=r"(r[0]), "=r"(r[1]), "=r"(r[2]), "=r"(r[3]) : "r"(addr));
}
__device__ __forceinline__ void hmma(float* c, const uint32_t* a, const uint32_t* b) {
    asm volatile(
        "mma.sync.aligned.m16n8k16.row.col.f32.f16.f16.f32 "
        "{%0,%1,%2,%3}, {%4,%5,%6,%7}, {%8,%9}, {%0,%1,%2,%3};"
        : "+f"(c[0]), "+f"(c[1]), "+f"(c[2]), "+f"(c[3])
        : "r"(a[0]), "r"(a[1]), "r"(a[2]), "r"(a[3]), "r"(b[0]), "r"(b[1]));
}
__device__ __forceinline__ void mbar_init(uint32_t a, uint32_t cnt) {
    asm volatile("mbarrier.init.shared.b64 [%0], %1;" :: "r"(a), "r"(cnt) : "memory");
}
__device__ __forceinline__ void mbar_arrive(uint32_t a) {
    asm volatile("mbarrier.arrive.release.cta.shared::cta.b64 _, [%0];" :: "r"(a) : "memory");
}
__device__ __forceinline__ void mbar_wait(uint32_t a, uint32_t parity) {
    asm volatile(
        "{\n\t.reg .pred P1;\n\t"
        "WL_%=:\n\t"
        "mbarrier.try_wait.parity.acquire.cta.shared::cta.b64 P1, [%0], %1, 0x989680;\n\t"
        "@P1 bra.uni WD_%=;\n\t"
        "bra.uni WL_%=;\n\t"
        "WD_%=:\n\t}"
        :: "r"(a), "r"(parity) : "memory");
}
__device__ __forceinline__ void barsync(int id, int cnt) {
    asm volatile("bar.sync %0, %1;" :: "r"(id), "r"(cnt) : "memory");
}

// -------- kernel 0: per-batch context mean --------
__global__ void k_ctx(const float* __restrict__ ctx) {
    int b = blockIdx.x;
    const float4* p = reinterpret_cast<const float4*>(ctx + (size_t)b * Cc);
    float4 v = p[threadIdx.x];
    float s = v.x + v.y + v.z + v.w;
    #pragma unroll
    for (int off = 16; off; off >>= 1) s += __shfl_down_sync(0xffffffffu, s, off);
    __shared__ float sm[4];
    if ((threadIdx.x & 31) == 0) sm[threadIdx.x >> 5] = s;
    __syncthreads();
    if (threadIdx.x == 0)
        g_ctx_mean[b] = (sm[0] + sm[1] + sm[2] + sm[3]) * (1.0f / Cc);
}

// -------- kernel 1: mean astro per o --------
__global__ void k_astro(const float* __restrict__ aact,
                        const float* __restrict__ athr) {
    int o = blockIdx.x * blockDim.x + threadIdx.x;
    float act = aact[o];
    float thr = athr[o];
    float s = 0.0f;
    #pragma unroll 8
    for (int b = 0; b < Bb; b++) {
        float a = 1.0f / (1.0f + expf(-g_ctx_mean[b] * act));
        s += (a > thr) ? a : 0.0f;
    }
    g_mean_astro[o] = s * (1.0f / Bb);
}

// -------- kernel 2: x -> fp16 hi/lo split --------
__global__ void k_xsplit(const float* __restrict__ x) {
    int e = blockIdx.x * blockDim.x + threadIdx.x;
    float2 v = reinterpret_cast<const float2*>(x)[e];
    uint32_t h = cvt_f16x2(v.y, v.x);
    __half2 h2 = *reinterpret_cast<__half2*>(&h);
    float2 hf = __half22float2(h2);
    uint32_t l = cvt_f16x2(v.y - hf.y, v.x - hf.x);
    g_xhi[e] = h;
    g_xlo[e] = l;
}

// -------- main warp-specialized fp16 tensor kernel, 4-stage ring --------
__global__ void __launch_bounds__(NTHREADS, 1)
k_main(const float* __restrict__ dend,
       const float* __restrict__ weight,
       const float* __restrict__ cstr,
       const float* __restrict__ pthr,
       const float* __restrict__ gates,
       const float* __restrict__ bias,
       float* __restrict__ out) {
    extern __shared__ char smraw[];
    uint32_t sb0 = sa(smraw);
    uint32_t sb = (sb0 + 1023u) & ~1023u;
    float* epf = reinterpret_cast<float*>(smraw + (sb - sb0) + SM_EP);

    const int t = threadIdx.x;
    const int lane = t & 31;
    const int o_base = blockIdx.x * No;

    const uint32_t FULLB = sb + SM_BAR;        // full[st] = FULLB + st*8
    const uint32_t EMPTYB = sb + SM_BAR + 32;  // empty[st] = EMPTYB + st*8
    const uint32_t aHi0 = sb + SM_A;
    const uint32_t aLo0 = sb + SM_A + STAGES * A_TILE;
    const uint32_t bT0 = sb + SM_B;

    if (t < 2 * STAGES) {
        // full: 4 producer-warp arrivals; empty: 8 consumer-warp arrivals
        mbar_init(sb + SM_BAR + t * 8, (t < STAGES) ? 4u : 8u);
    }
    // zero pad column rows (n % 12 == 11) of all B buffers, once
    for (int e = t; e < No * 8 * STAGES; e += NTHREADS) {
        int st = e >> 7, rem = e & 127, ol = rem >> 3, seg = rem & 7;
        uint32_t n = (uint32_t)(ol * NCOL + 11);
        stsz16(bT0 + st * B_TILE + swz(n * 128 + seg * 16));
    }
    __syncthreads();

    if (t < 256) {
        // ================= CONSUMER (8 warps) =================
        const int w = t >> 5;
        const int wm = w & 1;
        const int wn = w >> 1;

        float acc[2][6][4];
        #pragma unroll
        for (int mt = 0; mt < 2; mt++)
            #pragma unroll
            for (int nt = 0; nt < 6; nt++)
                acc[mt][nt][0] = acc[mt][nt][1] = acc[mt][nt][2] = acc[mt][nt][3] = 0.0f;

        const int grp = lane >> 3;
        const uint32_t arow0 = (uint32_t)((wm * 32 + (lane & 15)) * 128 + (lane >> 4) * 16);
        const uint32_t arow1 = arow0 + 16 * 128;
        const uint32_t brow = (uint32_t)((wn * 48 + (grp >> 1) * 8 + (lane & 7)) * 128
                                         + (grp & 1) * 16);

        for (int c = 0; c < NCHUNKS; c++) {
            const int st = c & (STAGES - 1);
            mbar_wait(FULLB + st * 8, (c >> 2) & 1);

            const uint32_t ahb = aHi0 + st * A_TILE;
            const uint32_t alb = aLo0 + st * A_TILE;
            const uint32_t bb = bT0 + st * B_TILE;
            #pragma unroll
            for (int ks = 0; ks < 4; ks++) {
                uint32_t ah0[4], al0[4], ah1[4], al1[4];
                uint32_t asw0 = swz(arow0 + ks * 32);
                uint32_t asw1 = swz(arow1 + ks * 32);
                ldsm4(ah0, ahb + asw0);
                ldsm4(al0, alb + asw0);
                ldsm4(ah1, ahb + asw1);
                ldsm4(al1, alb + asw1);
                #pragma unroll
                for (int pr = 0; pr < 3; pr++) {
                    uint32_t b4[4];
                    ldsm4(b4, bb + swz(brow + (uint32_t)pr * 2048 + ks * 32));
                    hmma(acc[0][2*pr],   ah0, b4);
                    hmma(acc[0][2*pr],   al0, b4);
                    hmma(acc[0][2*pr+1], ah0, b4 + 2);
                    hmma(acc[0][2*pr+1], al0, b4 + 2);
                    hmma(acc[1][2*pr],   ah1, b4);
                    hmma(acc[1][2*pr],   al1, b4);
                    hmma(acc[1][2*pr+1], ah1, b4 + 2);
                    hmma(acc[1][2*pr+1], al1, b4 + 2);
                }
            }
            __syncwarp();
            if (lane == 0) mbar_arrive(EMPTYB + st * 8);
        }

        // ---- epilogue ----
        barsync(5, 256);
        #pragma unroll
        for (int mt = 0; mt < 2; mt++) {
            int row = wm * 32 + mt * 16 + (lane >> 2);
            #pragma unroll
            for (int nt = 0; nt < 6; nt++) {
                int col = wn * 48 + nt * 8 + 2 * (lane & 3);
                stsv2(sb + SM_EP + (uint32_t)((row * EPW + col) * 4),
                      acc[mt][nt][0], acc[mt][nt][1]);
                stsv2(sb + SM_EP + (uint32_t)(((row + 8) * EPW + col) * 4),
                      acc[mt][nt][2], acc[mt][nt][3]);
            }
        }
        barsync(5, 256);

        {
            const int ol = t & 15;
            const int bg = t >> 4;
            const int oo = o_base + ol;
            const float ma = g_mean_astro[oo];
            const float bv = bias[oo];
            float sg[Ss];
            #pragma unroll
            for (int s = 0; s < Ss; s++) sg[s] = sigmoidf_(gates[oo * Ss + s]);
            #pragma unroll
            for (int j = 0; j < 4; j++) {
                int b = bg * 4 + j;
                const float* e = epf + b * EPW + ol * NCOL;
                float v = fmaf(e[10], ma, bv);
                #pragma unroll
                for (int s = 0; s < Ss; s++)
                    v = fmaf(sg[s], fmaxf(e[s], 0.0f), v);
                out[(size_t)b * Oo + oo] = fmaxf(v, 0.0f);
            }
        }
    } else {
        // ================= PRODUCER (4 warps) =================
        const int p = t - 256;
        const int o_loc = p >> 3;
        const int qp = p & 7;            // q = 2qp, 2qp+1 (k = 4q..4q+3)
        const int o = o_base + o_loc;
        const int nrow = o_loc * NCOL;
        const float thr = pthr[0];

        for (int c = 0; c < NCHUNKS; c++) {
            const int st = c & (STAGES - 1);
            const int kb = c * KCH;
            if (c >= STAGES)
                mbar_wait(EMPTYB + st * 8, ((c - STAGES) >> 2) & 1);

            // A tiles: x_hi/x_lo fp16, 1024 x 16B over 128 threads
            #pragma unroll
            for (int r = 0; r < 8; r++) {
                int idx = p + 128 * r;
                int op = idx >> 9;
                int g = idx & 511;
                int b = g >> 3, sg_ = g & 7;
                const char* src = reinterpret_cast<const char*>(op ? g_xlo : g_xhi)
                                + ((size_t)b * Ii + kb + sg_ * 8) * 2;
                cpa16((op ? aLo0 : aHi0) + st * A_TILE + swz((uint32_t)b * 128 + sg_ * 16), src);
            }
            cpa_commit();

            const int q0 = qp * 2, q1 = q0 + 1;
            float4 dA[10], dB[10];
            const float4* pA = reinterpret_cast<const float4*>(
                dend + ((size_t)o * Ii + kb + 4 * q0) * Ss);
            const float4* pB = reinterpret_cast<const float4*>(
                dend + ((size_t)o * Ii + kb + 4 * q1) * Ss);
            #pragma unroll
            for (int j = 0; j < 10; j++) dA[j] = pA[j];
            #pragma unroll
            for (int j = 0; j < 10; j++) dB[j] = pB[j];
            float4 wA = *reinterpret_cast<const float4*>(weight + (size_t)o * Ii + kb + 4 * q0);
            float4 cA = *reinterpret_cast<const float4*>(cstr   + (size_t)o * Ii + kb + 4 * q0);
            float4 wB = *reinterpret_cast<const float4*>(weight + (size_t)o * Ii + kb + 4 * q1);
            float4 cB = *reinterpret_cast<const float4*>(cstr   + (size_t)o * Ii + kb + 4 * q1);

            const uint32_t bb = bT0 + st * B_TILE;
            #pragma unroll
            for (int half = 0; half < 2; half++) {
                const float4* dr = half ? dB : dA;
                float4 w4 = half ? wB : wA;
                float4 c4 = half ? cB : cA;
                const int q = half ? q1 : q0;
                float f[40];
                #pragma unroll
                for (int j = 0; j < 10; j++) {
                    f[4*j] = dr[j].x; f[4*j+1] = dr[j].y;
                    f[4*j+2] = dr[j].z; f[4*j+3] = dr[j].w;
                }
                float wv[4];
                wv[0] = (fabsf(w4.x) * c4.x > thr) ? w4.x : 0.0f;
                wv[1] = (fabsf(w4.y) * c4.y > thr) ? w4.y : 0.0f;
                wv[2] = (fabsf(w4.z) * c4.z > thr) ? w4.z : 0.0f;
                wv[3] = (fabsf(w4.w) * c4.w > thr) ? w4.w : 0.0f;
                #pragma unroll
                for (int s = 0; s < 11; s++) {
                    float a0, a1, a2, a3;
                    if (s < 10) { a0 = f[s]; a1 = f[10+s]; a2 = f[20+s]; a3 = f[30+s]; }
                    else        { a0 = wv[0]; a1 = wv[1]; a2 = wv[2]; a3 = wv[3]; }
                    uint32_t h0 = cvt_f16x2(a1, a0);
                    uint32_t h1 = cvt_f16x2(a3, a2);
                    sts64(bb + swz((uint32_t)(nrow + s) * 128 + q * 8), h0, h1);
                }
            }
            cpa_waitg0();
            __syncwarp();
            if (lane == 0) mbar_arrive(FULLB + st * 8);
        }
    }
}

extern "C" void kernel_launch(void* const* d_in, const int* in_sizes, int n_in,
                              void* d_out, int out_size) {
    const float* x      = (const float*)d_in[0];
    const float* ctx    = (const float*)d_in[1];
    const float* weight = (const float*)d_in[3];
    const float* bias   = (const float*)d_in[4];
    const float* aact   = (const float*)d_in[5];
    const float* athr   = (const float*)d_in[6];
    const float* dend   = (const float*)d_in[7];
    const float* gates  = (const float*)d_in[8];
    const float* cstr   = (const float*)d_in[9];
    const float* pthr   = (const float*)d_in[10];
    float* out = (float*)d_out;

    cudaFuncSetAttribute(k_main, cudaFuncAttributeMaxDynamicSharedMemorySize, SMEM_REQ);

    k_ctx<<<Bb, 128>>>(ctx);
    k_astro<<<Oo / 256, 256>>>(aact, athr);
    k_xsplit<<<(Bb * Ii / 2) / 256, 256>>>(x);
    k_main<<<Oo / No, NTHREADS, SMEM_REQ>>>(dend, weight, cstr, pthr, gates, bias, out);
}

// round 10
// speedup vs baseline: 2.5496x; 1.0594x over previous
#include <cuda_runtime.h>
#include <cuda_fp16.h>
#include <cstdint>

// Problem constants
#define Bb 64
#define Ii 2048
#define Oo 2048
#define Ss 10
#define Cc 512

// Tiling
#define No 16                 // o's per CTA
#define NCOL 12               // cols per o: 10 seg + w + pad
#define KCH 64                // K chunk
#define NCHUNKS (Ii / KCH)    // 32
#define STAGES 4

// smem layout (byte offsets from 1024-aligned base)
#define A_TILE 8192           // 64 rows x 128 B (fp16 [b][k] SW128)
#define B_TILE 24576          // 192 rows x 128 B (fp16 [n][k] SW128)
#define SM_BAR 0              // full[st]@st*8, empty[st]@32+st*8
#define SM_A 1024             // a[0..3]
#define SM_B (SM_A + STAGES * A_TILE)      // 33792
#define SM_EP SM_A            // epilogue fp32 [64][EPW] overlays A+B region
#define EPW 196
#define SM_MA (SM_EP + Bb * EPW * 4)       // 16 floats mean-astro
#define SMEM_REQ (SM_B + STAGES * B_TILE + 1024)   // 133120

#define NTHREADS 384          // warps 0-7 consumers (MMA), 8-11 producers

// -------- scratch globals --------
__device__ float g_ctx_mean[Bb];
__device__ uint32_t g_xh[Bb * Ii / 2];    // fp16x2 [b][k]

// -------- helpers --------
__device__ __forceinline__ uint32_t sa(const void* p) {
    return (uint32_t)__cvta_generic_to_shared(p);
}
__device__ __forceinline__ void cpa16(uint32_t dst, const void* src) {
    asm volatile("cp.async.cg.shared.global [%0], [%1], 16;\n" :: "r"(dst), "l"(src));
}
__device__ __forceinline__ void cpa_commit() {
    asm volatile("cp.async.commit_group;\n" ::: "memory");
}
__device__ __forceinline__ void cpa_waitg0() {
    asm volatile("cp.async.wait_group 0;\n" ::: "memory");
}
__device__ __forceinline__ uint32_t cvt_f16x2(float hi, float lo) {
    uint32_t r;
    asm("cvt.rn.f16x2.f32 %0, %1, %2;" : "=r"(r) : "f"(hi), "f"(lo));
    return r;
}
__device__ __forceinline__ void sts64(uint32_t addr, uint32_t lo, uint32_t hi) {
    asm volatile("{\n\t.reg .b64 v;\n\tmov.b64 v, {%1, %2};\n\t"
                 "st.shared.b64 [%0], v;\n\t}" :: "r"(addr), "r"(lo), "r"(hi) : "memory");
}
__device__ __forceinline__ void stsv2(uint32_t addr, float x, float y) {
    asm volatile("st.shared.v2.f32 [%0], {%1, %2};" :: "r"(addr), "f"(x), "f"(y) : "memory");
}
__device__ __forceinline__ void stsz16(uint32_t addr) {
    asm volatile("st.shared.v4.b32 [%0], {%1, %1, %1, %1};" :: "r"(addr), "r"(0u) : "memory");
}
__device__ __forceinline__ uint32_t swz(uint32_t off) {
    return off ^ ((off >> 3) & 0x70);
}
__device__ __forceinline__ float sigmoidf_(float z) {
    return 1.0f / (1.0f + __expf(-z));
}
__device__ __forceinline__ void ldsm4(uint32_t* r, uint32_t addr) {
    asm volatile("ldmatrix.sync.aligned.m8n8.x4.shared.b16 {%0,%1,%2,%3}, [%4];"
                 : "=r"(r[0]), "=r"(r[1]), "=r"(r[2]), "=r"(r[3]) : "r"(addr));
}
__device__ __forceinline__ void hmma(float* c, const uint32_t* a, const uint32_t* b) {
    asm volatile(
        "mma.sync.aligned.m16n8k16.row.col.f32.f16.f16.f32 "
        "{%0,%1,%2,%3}, {%4,%5,%6,%7}, {%8,%9}, {%0,%1,%2,%3};"
        : "+f"(c[0]), "+f"(c[1]), "+f"(c[2]), "+f"(c[3])
        : "r"(a[0]), "r"(a[1]), "r"(a[2]), "r"(a[3]), "r"(b[0]), "r"(b[1]));
}
__device__ __forceinline__ void mbar_init(uint32_t a, uint32_t cnt) {
    asm volatile("mbarrier.init.shared.b64 [%0], %1;" :: "r"(a), "r"(cnt) : "memory");
}
__device__ __forceinline__ void mbar_arrive(uint32_t a) {
    asm volatile("mbarrier.arrive.release.cta.shared::cta.b64 _, [%0];" :: "r"(a) : "memory");
}
__device__ __forceinline__ void mbar_wait(uint32_t a, uint32_t parity) {
    asm volatile(
        "{\n\t.reg .pred P1;\n\t"
        "WL_%=:\n\t"
        "mbarrier.try_wait.parity.acquire.cta.shared::cta.b64 P1, [%0], %1, 0x989680;\n\t"
        "@P1 bra.uni WD_%=;\n\t"
        "bra.uni WL_%=;\n\t"
        "WD_%=:\n\t}"
        :: "r"(a), "r"(parity) : "memory");
}
__device__ __forceinline__ void barsync(int id, int cnt) {
    asm volatile("bar.sync %0, %1;" :: "r"(id), "r"(cnt) : "memory");
}

// -------- prep kernel: ctx mean (per batch) + x -> fp16 --------
__global__ void k_prep(const float* __restrict__ ctx, const float* __restrict__ x) {
    int b = blockIdx.x;                  // 64 blocks, 256 threads
    int t = threadIdx.x;
    // x convert: 1024 fp16x2 per row, 4 per thread
    #pragma unroll
    for (int i = 0; i < 4; i++) {
        int e = t + 256 * i;
        float2 v = reinterpret_cast<const float2*>(x + (size_t)b * Ii)[e];
        g_xh[b * (Ii / 2) + e] = cvt_f16x2(v.y, v.x);
    }
    // ctx mean (first 128 threads)
    __shared__ float sm[4];
    if (t < 128) {
        float4 v = reinterpret_cast<const float4*>(ctx + (size_t)b * Cc)[t];
        float s = v.x + v.y + v.z + v.w;
        #pragma unroll
        for (int off = 16; off; off >>= 1) s += __shfl_down_sync(0xffffffffu, s, off);
        if ((t & 31) == 0) sm[t >> 5] = s;
    }
    __syncthreads();
    if (t == 0)
        g_ctx_mean[b] = (sm[0] + sm[1] + sm[2] + sm[3]) * (1.0f / Cc);
}

// -------- main warp-specialized fp16 tensor kernel, 4-stage ring --------
__global__ void __launch_bounds__(NTHREADS, 1)
k_main(const float* __restrict__ dend,
       const float* __restrict__ weight,
       const float* __restrict__ cstr,
       const float* __restrict__ pthr,
       const float* __restrict__ gates,
       const float* __restrict__ bias,
       const float* __restrict__ aact,
       const float* __restrict__ athr,
       float* __restrict__ out) {
    extern __shared__ char smraw[];
    uint32_t sb0 = sa(smraw);
    uint32_t sb = (sb0 + 1023u) & ~1023u;
    float* epf = reinterpret_cast<float*>(smraw + (sb - sb0) + SM_EP);
    float* maf = reinterpret_cast<float*>(smraw + (sb - sb0) + SM_MA);

    const int t = threadIdx.x;
    const int lane = t & 31;
    const int o_base = blockIdx.x * No;

    const uint32_t FULLB = sb + SM_BAR;
    const uint32_t EMPTYB = sb + SM_BAR + 32;
    const uint32_t aT0 = sb + SM_A;
    const uint32_t bT0 = sb + SM_B;

    if (t < 2 * STAGES) {
        mbar_init(sb + SM_BAR + t * 8, (t < STAGES) ? 4u : 8u);
    }
    // zero pad column rows (n % 12 == 11) of all B buffers, once
    for (int e = t; e < No * 8 * STAGES; e += NTHREADS) {
        int st = e >> 7, rem = e & 127, ol = rem >> 3, seg = rem & 7;
        uint32_t n = (uint32_t)(ol * NCOL + 11);
        stsz16(bT0 + st * B_TILE + swz(n * 128 + seg * 16));
    }
    __syncthreads();

    if (t < 256) {
        // ================= CONSUMER (8 warps) =================
        const int w = t >> 5;
        const int wm = w & 1;
        const int wn = w >> 1;

        float acc[2][6][4];
        #pragma unroll
        for (int mt = 0; mt < 2; mt++)
            #pragma unroll
            for (int nt = 0; nt < 6; nt++)
                acc[mt][nt][0] = acc[mt][nt][1] = acc[mt][nt][2] = acc[mt][nt][3] = 0.0f;

        const int grp = lane >> 3;
        const uint32_t arow0 = (uint32_t)((wm * 32 + (lane & 15)) * 128 + (lane >> 4) * 16);
        const uint32_t arow1 = arow0 + 16 * 128;
        const uint32_t brow = (uint32_t)((wn * 48 + (grp >> 1) * 8 + (lane & 7)) * 128
                                         + (grp & 1) * 16);

        for (int c = 0; c < NCHUNKS; c++) {
            const int st = c & (STAGES - 1);
            mbar_wait(FULLB + st * 8, (c >> 2) & 1);

            const uint32_t ab = aT0 + st * A_TILE;
            const uint32_t bb = bT0 + st * B_TILE;
            #pragma unroll
            for (int ks = 0; ks < 4; ks++) {
                uint32_t a0[4], a1[4];
                ldsm4(a0, ab + swz(arow0 + ks * 32));
                ldsm4(a1, ab + swz(arow1 + ks * 32));
                #pragma unroll
                for (int pr = 0; pr < 3; pr++) {
                    uint32_t b4[4];
                    ldsm4(b4, bb + swz(brow + (uint32_t)pr * 2048 + ks * 32));
                    hmma(acc[0][2*pr],   a0, b4);
                    hmma(acc[0][2*pr+1], a0, b4 + 2);
                    hmma(acc[1][2*pr],   a1, b4);
                    hmma(acc[1][2*pr+1], a1, b4 + 2);
                }
            }
            __syncwarp();
            if (lane == 0) mbar_arrive(EMPTYB + st * 8);
        }

        // ---- epilogue: dump accumulators, compute mean-astro, combine ----
        barsync(5, 256);
        #pragma unroll
        for (int mt = 0; mt < 2; mt++) {
            int row = wm * 32 + mt * 16 + (lane >> 2);
            #pragma unroll
            for (int nt = 0; nt < 6; nt++) {
                int col = wn * 48 + nt * 8 + 2 * (lane & 3);
                stsv2(sb + SM_EP + (uint32_t)((row * EPW + col) * 4),
                      acc[mt][nt][0], acc[mt][nt][1]);
                stsv2(sb + SM_EP + (uint32_t)(((row + 8) * EPW + col) * 4),
                      acc[mt][nt][2], acc[mt][nt][3]);
            }
        }
        if (t < 16) {
            // mean astro for o = o_base + t
            float act = aact[o_base + t];
            float thv = athr[o_base + t];
            float s = 0.0f;
            #pragma unroll 8
            for (int b = 0; b < Bb; b++) {
                float a = 1.0f / (1.0f + expf(-g_ctx_mean[b] * act));
                s += (a > thv) ? a : 0.0f;
            }
            maf[t] = s * (1.0f / Bb);
        }
        barsync(5, 256);

        {
            const int ol = t & 15;
            const int bg = t >> 4;
            const int oo = o_base + ol;
            const float ma = maf[ol];
            const float bv = bias[oo];
            float sg[Ss];
            #pragma unroll
            for (int s = 0; s < Ss; s++) sg[s] = sigmoidf_(gates[oo * Ss + s]);
            #pragma unroll
            for (int j = 0; j < 4; j++) {
                int b = bg * 4 + j;
                const float* e = epf + b * EPW + ol * NCOL;
                float v = fmaf(e[10], ma, bv);
                #pragma unroll
                for (int s = 0; s < Ss; s++)
                    v = fmaf(sg[s], fmaxf(e[s], 0.0f), v);
                out[(size_t)b * Oo + oo] = fmaxf(v, 0.0f);
            }
        }
    } else {
        // ================= PRODUCER (4 warps) =================
        const int p = t - 256;
        const int o_loc = p >> 3;
        const int qp = p & 7;            // q = 2qp, 2qp+1 (k = 4q..4q+3)
        const int o = o_base + o_loc;
        const int nrow = o_loc * NCOL;
        const float thr = pthr[0];

        for (int c = 0; c < NCHUNKS; c++) {
            const int st = c & (STAGES - 1);
            const int kb = c * KCH;
            if (c >= STAGES)
                mbar_wait(EMPTYB + st * 8, ((c - STAGES) >> 2) & 1);

            // A tile: x fp16, 512 x 16B over 128 threads
            #pragma unroll
            for (int r = 0; r < 4; r++) {
                int g = p + 128 * r;              // 0..511
                int b = g >> 3, sg_ = g & 7;
                const char* src = reinterpret_cast<const char*>(g_xh)
                                + ((size_t)b * Ii + kb + sg_ * 8) * 2;
                cpa16(aT0 + st * A_TILE + swz((uint32_t)b * 128 + sg_ * 16), src);
            }
            cpa_commit();

            const int q0 = qp * 2, q1 = q0 + 1;
            float4 dA[10], dB[10];
            const float4* pA = reinterpret_cast<const float4*>(
                dend + ((size_t)o * Ii + kb + 4 * q0) * Ss);
            const float4* pB = reinterpret_cast<const float4*>(
                dend + ((size_t)o * Ii + kb + 4 * q1) * Ss);
            #pragma unroll
            for (int j = 0; j < 10; j++) dA[j] = pA[j];
            #pragma unroll
            for (int j = 0; j < 10; j++) dB[j] = pB[j];
            float4 wA = *reinterpret_cast<const float4*>(weight + (size_t)o * Ii + kb + 4 * q0);
            float4 cA = *reinterpret_cast<const float4*>(cstr   + (size_t)o * Ii + kb + 4 * q0);
            float4 wB = *reinterpret_cast<const float4*>(weight + (size_t)o * Ii + kb + 4 * q1);
            float4 cB = *reinterpret_cast<const float4*>(cstr   + (size_t)o * Ii + kb + 4 * q1);

            const uint32_t bb = bT0 + st * B_TILE;
            #pragma unroll
            for (int half = 0; half < 2; half++) {
                const float4* dr = half ? dB : dA;
                float4 w4 = half ? wB : wA;
                float4 c4 = half ? cB : cA;
                const int q = half ? q1 : q0;
                float f[40];
                #pragma unroll
                for (int j = 0; j < 10; j++) {
                    f[4*j] = dr[j].x; f[4*j+1] = dr[j].y;
                    f[4*j+2] = dr[j].z; f[4*j+3] = dr[j].w;
                }
                float wv[4];
                wv[0] = (fabsf(w4.x) * c4.x > thr) ? w4.x : 0.0f;
                wv[1] = (fabsf(w4.y) * c4.y > thr) ? w4.y : 0.0f;
                wv[2] = (fabsf(w4.z) * c4.z > thr) ? w4.z : 0.0f;
                wv[3] = (fabsf(w4.w) * c4.w > thr) ? w4.w : 0.0f;
                #pragma unroll
                for (int s = 0; s < 11; s++) {
                    float a0, a1, a2, a3;
                    if (s < 10) { a0 = f[s]; a1 = f[10+s]; a2 = f[20+s]; a3 = f[30+s]; }
                    else        { a0 = wv[0]; a1 = wv[1]; a2 = wv[2]; a3 = wv[3]; }
                    uint32_t h0 = cvt_f16x2(a1, a0);
                    uint32_t h1 = cvt_f16x2(a3, a2);
                    sts64(bb + swz((uint32_t)(nrow + s) * 128 + q * 8), h0, h1);
                }
            }
            cpa_waitg0();
            __syncwarp();
            if (lane == 0) mbar_arrive(FULLB + st * 8);
        }
    }
}

extern "C" void kernel_launch(void* const* d_in, const int* in_sizes, int n_in,
                              void* d_out, int out_size) {
    const float* x      = (const float*)d_in[0];
    const float* ctx    = (const float*)d_in[1];
    const float* weight = (const float*)d_in[3];
    const float* bias   = (const float*)d_in[4];
    const float* aact   = (const float*)d_in[5];
    const float* athr   = (const float*)d_in[6];
    const float* dend   = (const float*)d_in[7];
    const float* gates  = (const float*)d_in[8];
    const float* cstr   = (const float*)d_in[9];
    const float* pthr   = (const float*)d_in[10];
    float* out = (float*)d_out;

    cudaFuncSetAttribute(k_main, cudaFuncAttributeMaxDynamicSharedMemorySize, SMEM_REQ);

    k_prep<<<Bb, 256>>>(ctx, x);
    k_main<<<Oo / No, NTHREADS, SMEM_REQ>>>(dend, weight, cstr, pthr, gates, bias,
                                            aact, athr, out);
}

// round 11
// speedup vs baseline: 3.1358x; 1.2299x over previous
#include <cuda_runtime.h>
#include <cuda_fp16.h>
#include <cstdint>

// Problem constants
#define Bb 64
#define Ii 2048
#define Oo 2048
#define Ss 10
#define Cc 512

// Tiling
#define No 16                 // o's per CTA
#define NCOL 12               // cols per o: 10 seg + w + pad
#define KCH 64                // K chunk
#define NCHUNKS (Ii / KCH)    // 32
#define STAGES 4

// smem layout (byte offsets from 1024-aligned base)
#define A_TILE 8192           // 64 rows x 128 B (fp16 [b][k] SW128)
#define B_TILE 24576          // 192 rows x 128 B (fp16 [n][k] SW128)
#define SM_BAR 0              // full[st]@st*8, empty[st]@32+st*8
#define SM_A 1024             // a[0..3]
#define SM_B (SM_A + STAGES * A_TILE)      // 33792
#define SM_EP SM_A            // epilogue fp32 [64][EPW] overlays A+B region
#define EPW 196
#define SM_MA (SM_EP + Bb * EPW * 4)       // 16 floats mean-astro
#define SMEM_REQ (SM_B + STAGES * B_TILE + 1024)   // 133120

#define NTHREADS 512          // warps 0-7 consumers (MMA), 8-15 producers

// -------- scratch globals --------
__device__ float g_ctx_mean[Bb];
__device__ uint32_t g_xh[Bb * Ii / 2];    // fp16x2 [b][k]

// -------- helpers --------
__device__ __forceinline__ uint32_t sa(const void* p) {
    return (uint32_t)__cvta_generic_to_shared(p);
}
__device__ __forceinline__ void cpa16(uint32_t dst, const void* src) {
    asm volatile("cp.async.cg.shared.global [%0], [%1], 16;\n" :: "r"(dst), "l"(src));
}
__device__ __forceinline__ void cpa_commit() {
    asm volatile("cp.async.commit_group;\n" ::: "memory");
}
__device__ __forceinline__ void cpa_waitg0() {
    asm volatile("cp.async.wait_group 0;\n" ::: "memory");
}
__device__ __forceinline__ uint32_t cvt_f16x2(float hi, float lo) {
    uint32_t r;
    asm("cvt.rn.f16x2.f32 %0, %1, %2;" : "=r"(r) : "f"(hi), "f"(lo));
    return r;
}
__device__ __forceinline__ void sts64(uint32_t addr, uint32_t lo, uint32_t hi) {
    asm volatile("{\n\t.reg .b64 v;\n\tmov.b64 v, {%1, %2};\n\t"
                 "st.shared.b64 [%0], v;\n\t}" :: "r"(addr), "r"(lo), "r"(hi) : "memory");
}
__device__ __forceinline__ void stsv2(uint32_t addr, float x, float y) {
    asm volatile("st.shared.v2.f32 [%0], {%1, %2};" :: "r"(addr), "f"(x), "f"(y) : "memory");
}
__device__ __forceinline__ void stsz16(uint32_t addr) {
    asm volatile("st.shared.v4.b32 [%0], {%1, %1, %1, %1};" :: "r"(addr), "r"(0u) : "memory");
}
__device__ __forceinline__ uint32_t swz(uint32_t off) {
    return off ^ ((off >> 3) & 0x70);
}
__device__ __forceinline__ float sigmoidf_(float z) {
    return 1.0f / (1.0f + __expf(-z));
}
__device__ __forceinline__ void ldsm4(uint32_t* r, uint32_t addr) {
    asm volatile("ldmatrix.sync.aligned.m8n8.x4.shared.b16 {%0,%1,%2,%3}, [%4];"
                 : "=r"(r[0]), "=r"(r[1]), "=r"(r[2]), "=r"(r[3]) : "r"(addr));
}
__device__ __forceinline__ void hmma(float* c, const uint32_t* a, const uint32_t* b) {
    asm volatile(
        "mma.sync.aligned.m16n8k16.row.col.f32.f16.f16.f32 "
        "{%0,%1,%2,%3}, {%4,%5,%6,%7}, {%8,%9}, {%0,%1,%2,%3};"
        : "+f"(c[0]), "+f"(c[1]), "+f"(c[2]), "+f"(c[3])
        : "r"(a[0]), "r"(a[1]), "r"(a[2]), "r"(a[3]), "r"(b[0]), "r"(b[1]));
}
__device__ __forceinline__ void mbar_init(uint32_t a, uint32_t cnt) {
    asm volatile("mbarrier.init.shared.b64 [%0], %1;" :: "r"(a), "r"(cnt) : "memory");
}
__device__ __forceinline__ void mbar_arrive(uint32_t a) {
    asm volatile("mbarrier.arrive.release.cta.shared::cta.b64 _, [%0];" :: "r"(a) : "memory");
}
__device__ __forceinline__ void mbar_wait(uint32_t a, uint32_t parity) {
    asm volatile(
        "{\n\t.reg .pred P1;\n\t"
        "WL_%=:\n\t"
        "mbarrier.try_wait.parity.acquire.cta.shared::cta.b64 P1, [%0], %1, 0x989680;\n\t"
        "@P1 bra.uni WD_%=;\n\t"
        "bra.uni WL_%=;\n\t"
        "WD_%=:\n\t}"
        :: "r"(a), "r"(parity) : "memory");
}
__device__ __forceinline__ void barsync(int id, int cnt) {
    asm volatile("bar.sync %0, %1;" :: "r"(id), "r"(cnt) : "memory");
}

// -------- prep kernel: ctx mean (per batch) + x -> fp16 --------
__global__ void k_prep(const float* __restrict__ ctx, const float* __restrict__ x) {
    int b = blockIdx.x;                  // 64 blocks, 256 threads
    int t = threadIdx.x;
    #pragma unroll
    for (int i = 0; i < 4; i++) {
        int e = t + 256 * i;
        float2 v = reinterpret_cast<const float2*>(x + (size_t)b * Ii)[e];
        g_xh[b * (Ii / 2) + e] = cvt_f16x2(v.y, v.x);
    }
    __shared__ float sm[4];
    if (t < 128) {
        float4 v = reinterpret_cast<const float4*>(ctx + (size_t)b * Cc)[t];
        float s = v.x + v.y + v.z + v.w;
        #pragma unroll
        for (int off = 16; off; off >>= 1) s += __shfl_down_sync(0xffffffffu, s, off);
        if ((t & 31) == 0) sm[t >> 5] = s;
    }
    __syncthreads();
    if (t == 0)
        g_ctx_mean[b] = (sm[0] + sm[1] + sm[2] + sm[3]) * (1.0f / Cc);
}

// -------- main warp-specialized fp16 tensor kernel, 4-stage ring --------
// Warps 0-7: MMA consumers. Warps 8-15: producers, ONE (o, 4k) cell per
// thread per chunk (12 independent LDG.128, low reg pressure -> high MLP).
__global__ void __launch_bounds__(NTHREADS, 1)
k_main(const float* __restrict__ dend,
       const float* __restrict__ weight,
       const float* __restrict__ cstr,
       const float* __restrict__ pthr,
       const float* __restrict__ gates,
       const float* __restrict__ bias,
       const float* __restrict__ aact,
       const float* __restrict__ athr,
       float* __restrict__ out) {
    extern __shared__ char smraw[];
    uint32_t sb0 = sa(smraw);
    uint32_t sb = (sb0 + 1023u) & ~1023u;
    float* epf = reinterpret_cast<float*>(smraw + (sb - sb0) + SM_EP);
    float* maf = reinterpret_cast<float*>(smraw + (sb - sb0) + SM_MA);

    const int t = threadIdx.x;
    const int lane = t & 31;
    const int o_base = blockIdx.x * No;

    const uint32_t FULLB = sb + SM_BAR;
    const uint32_t EMPTYB = sb + SM_BAR + 32;
    const uint32_t aT0 = sb + SM_A;
    const uint32_t bT0 = sb + SM_B;

    if (t < 2 * STAGES) {
        // full: 8 producer-warp arrivals; empty: 8 consumer-warp arrivals
        mbar_init(sb + SM_BAR + t * 8, 8u);
    }
    // zero pad column rows (n % 12 == 11) of all B buffers, once
    for (int e = t; e < No * 8 * STAGES; e += NTHREADS) {
        int st = e >> 7, rem = e & 127, ol = rem >> 3, seg = rem & 7;
        uint32_t n = (uint32_t)(ol * NCOL + 11);
        stsz16(bT0 + st * B_TILE + swz(n * 128 + seg * 16));
    }
    __syncthreads();

    if (t < 256) {
        // ================= CONSUMER (8 warps) =================
        const int w = t >> 5;
        const int wm = w & 1;
        const int wn = w >> 1;

        float acc[2][6][4];
        #pragma unroll
        for (int mt = 0; mt < 2; mt++)
            #pragma unroll
            for (int nt = 0; nt < 6; nt++)
                acc[mt][nt][0] = acc[mt][nt][1] = acc[mt][nt][2] = acc[mt][nt][3] = 0.0f;

        const int grp = lane >> 3;
        const uint32_t arow0 = (uint32_t)((wm * 32 + (lane & 15)) * 128 + (lane >> 4) * 16);
        const uint32_t arow1 = arow0 + 16 * 128;
        const uint32_t brow = (uint32_t)((wn * 48 + (grp >> 1) * 8 + (lane & 7)) * 128
                                         + (grp & 1) * 16);

        for (int c = 0; c < NCHUNKS; c++) {
            const int st = c & (STAGES - 1);
            mbar_wait(FULLB + st * 8, (c >> 2) & 1);

            const uint32_t ab = aT0 + st * A_TILE;
            const uint32_t bb = bT0 + st * B_TILE;
            #pragma unroll
            for (int ks = 0; ks < 4; ks++) {
                uint32_t a0[4], a1[4];
                ldsm4(a0, ab + swz(arow0 + ks * 32));
                ldsm4(a1, ab + swz(arow1 + ks * 32));
                #pragma unroll
                for (int pr = 0; pr < 3; pr++) {
                    uint32_t b4[4];
                    ldsm4(b4, bb + swz(brow + (uint32_t)pr * 2048 + ks * 32));
                    hmma(acc[0][2*pr],   a0, b4);
                    hmma(acc[0][2*pr+1], a0, b4 + 2);
                    hmma(acc[1][2*pr],   a1, b4);
                    hmma(acc[1][2*pr+1], a1, b4 + 2);
                }
            }
            __syncwarp();
            if (lane == 0) mbar_arrive(EMPTYB + st * 8);
        }

        // ---- epilogue: dump accumulators, compute mean-astro, combine ----
        barsync(5, 256);
        #pragma unroll
        for (int mt = 0; mt < 2; mt++) {
            int row = wm * 32 + mt * 16 + (lane >> 2);
            #pragma unroll
            for (int nt = 0; nt < 6; nt++) {
                int col = wn * 48 + nt * 8 + 2 * (lane & 3);
                stsv2(sb + SM_EP + (uint32_t)((row * EPW + col) * 4),
                      acc[mt][nt][0], acc[mt][nt][1]);
                stsv2(sb + SM_EP + (uint32_t)(((row + 8) * EPW + col) * 4),
                      acc[mt][nt][2], acc[mt][nt][3]);
            }
        }
        if (t < 16) {
            float act = aact[o_base + t];
            float thv = athr[o_base + t];
            float s = 0.0f;
            #pragma unroll 8
            for (int b = 0; b < Bb; b++) {
                float a = 1.0f / (1.0f + expf(-g_ctx_mean[b] * act));
                s += (a > thv) ? a : 0.0f;
            }
            maf[t] = s * (1.0f / Bb);
        }
        barsync(5, 256);

        {
            const int ol = t & 15;
            const int bg = t >> 4;
            const int oo = o_base + ol;
            const float ma = maf[ol];
            const float bv = bias[oo];
            float sg[Ss];
            #pragma unroll
            for (int s = 0; s < Ss; s++) sg[s] = sigmoidf_(gates[oo * Ss + s]);
            #pragma unroll
            for (int j = 0; j < 4; j++) {
                int b = bg * 4 + j;
                const float* e = epf + b * EPW + ol * NCOL;
                float v = fmaf(e[10], ma, bv);
                #pragma unroll
                for (int s = 0; s < Ss; s++)
                    v = fmaf(sg[s], fmaxf(e[s], 0.0f), v);
                out[(size_t)b * Oo + oo] = fmaxf(v, 0.0f);
            }
        }
    } else {
        // ================= PRODUCER (8 warps) =================
        const int p = t - 256;           // 0..255
        const int o_loc = p >> 4;        // 0..15
        const int q = p & 15;            // k-quarter: k = 4q..4q+3
        const int o = o_base + o_loc;
        const int nrow = o_loc * NCOL;
        const float thr = pthr[0];
        const float* dsrc = dend + ((size_t)o * Ii + 4 * q) * Ss;
        const float* wsrc = weight + (size_t)o * Ii + 4 * q;
        const float* csrc = cstr + (size_t)o * Ii + 4 * q;

        for (int c = 0; c < NCHUNKS; c++) {
            const int st = c & (STAGES - 1);
            const int kb = c * KCH;
            if (c >= STAGES)
                mbar_wait(EMPTYB + st * 8, ((c - STAGES) >> 2) & 1);

            // A tile: x fp16, 512 x 16B over 256 threads
            #pragma unroll
            for (int r = 0; r < 2; r++) {
                int g = p + 256 * r;              // 0..511
                int b = g >> 3, sg_ = g & 7;
                const char* src = reinterpret_cast<const char*>(g_xh)
                                + ((size_t)b * Ii + kb + sg_ * 8) * 2;
                cpa16(aT0 + st * A_TILE + swz((uint32_t)b * 128 + sg_ * 16), src);
            }
            cpa_commit();

            // one (o, 4k) cell: 12 independent LDG.128
            float4 d4[10];
            const float4* dp4 = reinterpret_cast<const float4*>(dsrc + (size_t)kb * Ss);
            #pragma unroll
            for (int j = 0; j < 10; j++) d4[j] = dp4[j];
            float4 w4 = *reinterpret_cast<const float4*>(wsrc + kb);
            float4 c4 = *reinterpret_cast<const float4*>(csrc + kb);

            float f[40];
            #pragma unroll
            for (int j = 0; j < 10; j++) {
                f[4*j] = d4[j].x; f[4*j+1] = d4[j].y;
                f[4*j+2] = d4[j].z; f[4*j+3] = d4[j].w;
            }
            float wv[4];
            wv[0] = (fabsf(w4.x) * c4.x > thr) ? w4.x : 0.0f;
            wv[1] = (fabsf(w4.y) * c4.y > thr) ? w4.y : 0.0f;
            wv[2] = (fabsf(w4.z) * c4.z > thr) ? w4.z : 0.0f;
            wv[3] = (fabsf(w4.w) * c4.w > thr) ? w4.w : 0.0f;

            const uint32_t bb = bT0 + st * B_TILE;
            #pragma unroll
            for (int s = 0; s < 11; s++) {
                float a0, a1, a2, a3;
                if (s < 10) { a0 = f[s]; a1 = f[10+s]; a2 = f[20+s]; a3 = f[30+s]; }
                else        { a0 = wv[0]; a1 = wv[1]; a2 = wv[2]; a3 = wv[3]; }
                uint32_t h0 = cvt_f16x2(a1, a0);
                uint32_t h1 = cvt_f16x2(a3, a2);
                sts64(bb + swz((uint32_t)(nrow + s) * 128 + q * 8), h0, h1);
            }

            cpa_waitg0();
            __syncwarp();
            if (lane == 0) mbar_arrive(FULLB + st * 8);
        }
    }
}

extern "C" void kernel_launch(void* const* d_in, const int* in_sizes, int n_in,
                              void* d_out, int out_size) {
    const float* x      = (const float*)d_in[0];
    const float* ctx    = (const float*)d_in[1];
    const float* weight = (const float*)d_in[3];
    const float* bias   = (const float*)d_in[4];
    const float* aact   = (const float*)d_in[5];
    const float* athr   = (const float*)d_in[6];
    const float* dend   = (const float*)d_in[7];
    const float* gates  = (const float*)d_in[8];
    const float* cstr   = (const float*)d_in[9];
    const float* pthr   = (const float*)d_in[10];
    float* out = (float*)d_out;

    cudaFuncSetAttribute(k_main, cudaFuncAttributeMaxDynamicSharedMemorySize, SMEM_REQ);

    k_prep<<<Bb, 256>>>(ctx, x);
    k_main<<<Oo / No, NTHREADS, SMEM_REQ>>>(dend, weight, cstr, pthr, gates, bias,
                                            aact, athr, out);
}

// round 12
// speedup vs baseline: 3.2408x; 1.0335x over previous
#include <cuda_runtime.h>
#include <cuda_fp16.h>
#include <cstdint>

// Problem constants
#define Bb 64
#define Ii 2048
#define Oo 2048
#define Ss 10
#define Cc 512

// Tiling
#define No 8                  // o's per CTA -> N = 96 cols
#define NCOL 12               // cols per o: 10 seg + w + pad
#define KCH 64                // K chunk
#define NCHUNKS (Ii / KCH)    // 32
#define STAGES 4

// smem layout (byte offsets from 1024-aligned base)
#define A_TILE 8192           // 64 rows x 128 B (fp16 [b][k] SW128)
#define B_TILE 12288          // 96 rows x 128 B (fp16 [n][k] SW128)
#define SM_BAR 0              // full[st]@st*8, empty[st]@32+st*8
#define SM_A 1024             // a[0..3]
#define SM_B (SM_A + STAGES * A_TILE)      // 33792
#define SM_EP SM_A            // epilogue fp32 [64][EPW] overlays A+B region
#define EPW 100
#define SM_MA (SM_EP + Bb * EPW * 4)       // 8 floats mean-astro
#define SMEM_REQ (SM_B + STAGES * B_TILE + 1024)   // 83968  (x2 CTAs = 168KB)

#define NTHREADS 256          // warps 0-3 consumers (MMA), 4-7 producers

// -------- scratch globals --------
__device__ float g_ctx_mean[Bb];
__device__ uint32_t g_xh[Bb * Ii / 2];    // fp16x2 [b][k]

// -------- helpers --------
__device__ __forceinline__ uint32_t sa(const void* p) {
    return (uint32_t)__cvta_generic_to_shared(p);
}
__device__ __forceinline__ void cpa16(uint32_t dst, const void* src) {
    asm volatile("cp.async.cg.shared.global [%0], [%1], 16;\n" :: "r"(dst), "l"(src));
}
__device__ __forceinline__ void cpa_commit() {
    asm volatile("cp.async.commit_group;\n" ::: "memory");
}
__device__ __forceinline__ void cpa_waitg0() {
    asm volatile("cp.async.wait_group 0;\n" ::: "memory");
}
__device__ __forceinline__ uint32_t cvt_f16x2(float hi, float lo) {
    uint32_t r;
    asm("cvt.rn.f16x2.f32 %0, %1, %2;" : "=r"(r) : "f"(hi), "f"(lo));
    return r;
}
__device__ __forceinline__ void sts64(uint32_t addr, uint32_t lo, uint32_t hi) {
    asm volatile("{\n\t.reg .b64 v;\n\tmov.b64 v, {%1, %2};\n\t"
                 "st.shared.b64 [%0], v;\n\t}" :: "r"(addr), "r"(lo), "r"(hi) : "memory");
}
__device__ __forceinline__ void stsv2(uint32_t addr, float x, float y) {
    asm volatile("st.shared.v2.f32 [%0], {%1, %2};" :: "r"(addr), "f"(x), "f"(y) : "memory");
}
__device__ __forceinline__ void stsz16(uint32_t addr) {
    asm volatile("st.shared.v4.b32 [%0], {%1, %1, %1, %1};" :: "r"(addr), "r"(0u) : "memory");
}
__device__ __forceinline__ uint32_t swz(uint32_t off) {
    return off ^ ((off >> 3) & 0x70);
}
__device__ __forceinline__ float sigmoidf_(float z) {
    return 1.0f / (1.0f + __expf(-z));
}
__device__ __forceinline__ void ldsm4(uint32_t* r, uint32_t addr) {
    asm volatile("ldmatrix.sync.aligned.m8n8.x4.shared.b16 {%0,%1,%2,%3}, [%4];"
                 : "=r"(r[0]), "=r"(r[1]), "=r"(r[2]), "=r"(r[3]) : "r"(addr));
}
__device__ __forceinline__ void hmma(float* c, const uint32_t* a, const uint32_t* b) {
    asm volatile(
        "mma.sync.aligned.m16n8k16.row.col.f32.f16.f16.f32 "
        "{%0,%1,%2,%3}, {%4,%5,%6,%7}, {%8,%9}, {%0,%1,%2,%3};"
        : "+f"(c[0]), "+f"(c[1]), "+f"(c[2]), "+f"(c[3])
        : "r"(a[0]), "r"(a[1]), "r"(a[2]), "r"(a[3]), "r"(b[0]), "r"(b[1]));
}
__device__ __forceinline__ void mbar_init(uint32_t a, uint32_t cnt) {
    asm volatile("mbarrier.init.shared.b64 [%0], %1;" :: "r"(a), "r"(cnt) : "memory");
}
__device__ __forceinline__ void mbar_arrive(uint32_t a) {
    asm volatile("mbarrier.arrive.release.cta.shared::cta.b64 _, [%0];" :: "r"(a) : "memory");
}
__device__ __forceinline__ void mbar_wait(uint32_t a, uint32_t parity) {
    asm volatile(
        "{\n\t.reg .pred P1;\n\t"
        "WL_%=:\n\t"
        "mbarrier.try_wait.parity.acquire.cta.shared::cta.b64 P1, [%0], %1, 0x989680;\n\t"
        "@P1 bra.uni WD_%=;\n\t"
        "bra.uni WL_%=;\n\t"
        "WD_%=:\n\t}"
        :: "r"(a), "r"(parity) : "memory");
}
__device__ __forceinline__ void barsync(int id, int cnt) {
    asm volatile("bar.sync %0, %1;" :: "r"(id), "r"(cnt) : "memory");
}

// -------- prep kernel: ctx mean (per batch) + x -> fp16 --------
__global__ void k_prep(const float* __restrict__ ctx, const float* __restrict__ x) {
    int b = blockIdx.x;                  // 64 blocks, 256 threads
    int t = threadIdx.x;
    #pragma unroll
    for (int i = 0; i < 4; i++) {
        int e = t + 256 * i;
        float2 v = reinterpret_cast<const float2*>(x + (size_t)b * Ii)[e];
        g_xh[b * (Ii / 2) + e] = cvt_f16x2(v.y, v.x);
    }
    __shared__ float sm[4];
    if (t < 128) {
        float4 v = reinterpret_cast<const float4*>(ctx + (size_t)b * Cc)[t];
        float s = v.x + v.y + v.z + v.w;
        #pragma unroll
        for (int off = 16; off; off >>= 1) s += __shfl_down_sync(0xffffffffu, s, off);
        if ((t & 31) == 0) sm[t >> 5] = s;
    }
    __syncthreads();
    if (t == 0)
        g_ctx_mean[b] = (sm[0] + sm[1] + sm[2] + sm[3]) * (1.0f / Cc);
}

// -------- main warp-specialized fp16 tensor kernel --------
// Grid 256 (No=8), 2 CTAs/SM. Warps 0-3: MMA consumers. Warps 4-7: producers,
// one (o, 4k) cell per thread per chunk (12 independent LDG.128).
__global__ void __launch_bounds__(NTHREADS, 2)
k_main(const float* __restrict__ dend,
       const float* __restrict__ weight,
       const float* __restrict__ cstr,
       const float* __restrict__ pthr,
       const float* __restrict__ gates,
       const float* __restrict__ bias,
       const float* __restrict__ aact,
       const float* __restrict__ athr,
       float* __restrict__ out) {
    extern __shared__ char smraw[];
    uint32_t sb0 = sa(smraw);
    uint32_t sb = (sb0 + 1023u) & ~1023u;
    float* epf = reinterpret_cast<float*>(smraw + (sb - sb0) + SM_EP);
    float* maf = reinterpret_cast<float*>(smraw + (sb - sb0) + SM_MA);

    const int t = threadIdx.x;
    const int lane = t & 31;
    const int o_base = blockIdx.x * No;

    const uint32_t FULLB = sb + SM_BAR;
    const uint32_t EMPTYB = sb + SM_BAR + 32;
    const uint32_t aT0 = sb + SM_A;
    const uint32_t bT0 = sb + SM_B;

    if (t < 2 * STAGES) {
        // full: 4 producer-warp arrivals; empty: 4 consumer-warp arrivals
        mbar_init(sb + SM_BAR + t * 8, 4u);
    }
    // zero pad column rows (n % 12 == 11) of all B buffers, once
    {
        int st = t >> 6, rem = t & 63, ol = rem >> 3, seg = rem & 7;  // 256 = 4*8*8
        uint32_t n = (uint32_t)(ol * NCOL + 11);
        stsz16(bT0 + st * B_TILE + swz(n * 128 + seg * 16));
    }
    __syncthreads();

    if (t < 128) {
        // ================= CONSUMER (4 warps) =================
        const int w = t >> 5;
        const int wm = w & 1;
        const int wn = w >> 1;

        float acc[2][6][4];
        #pragma unroll
        for (int mt = 0; mt < 2; mt++)
            #pragma unroll
            for (int nt = 0; nt < 6; nt++)
                acc[mt][nt][0] = acc[mt][nt][1] = acc[mt][nt][2] = acc[mt][nt][3] = 0.0f;

        const int grp = lane >> 3;
        const uint32_t arow0 = (uint32_t)((wm * 32 + (lane & 15)) * 128 + (lane >> 4) * 16);
        const uint32_t arow1 = arow0 + 16 * 128;
        const uint32_t brow = (uint32_t)((wn * 48 + (grp >> 1) * 8 + (lane & 7)) * 128
                                         + (grp & 1) * 16);

        for (int c = 0; c < NCHUNKS; c++) {
            const int st = c & (STAGES - 1);
            mbar_wait(FULLB + st * 8, (c >> 2) & 1);

            const uint32_t ab = aT0 + st * A_TILE;
            const uint32_t bb = bT0 + st * B_TILE;
            #pragma unroll
            for (int ks = 0; ks < 4; ks++) {
                uint32_t a0[4], a1[4];
                ldsm4(a0, ab + swz(arow0 + ks * 32));
                ldsm4(a1, ab + swz(arow1 + ks * 32));
                #pragma unroll
                for (int pr = 0; pr < 3; pr++) {
                    uint32_t b4[4];
                    ldsm4(b4, bb + swz(brow + (uint32_t)pr * 2048 + ks * 32));
                    hmma(acc[0][2*pr],   a0, b4);
                    hmma(acc[0][2*pr+1], a0, b4 + 2);
                    hmma(acc[1][2*pr],   a1, b4);
                    hmma(acc[1][2*pr+1], a1, b4 + 2);
                }
            }
            __syncwarp();
            if (lane == 0) mbar_arrive(EMPTYB + st * 8);
        }

        // ---- epilogue: dump accumulators, compute mean-astro, combine ----
        barsync(5, 128);
        #pragma unroll
        for (int mt = 0; mt < 2; mt++) {
            int row = wm * 32 + mt * 16 + (lane >> 2);
            #pragma unroll
            for (int nt = 0; nt < 6; nt++) {
                int col = wn * 48 + nt * 8 + 2 * (lane & 3);
                stsv2(sb + SM_EP + (uint32_t)((row * EPW + col) * 4),
                      acc[mt][nt][0], acc[mt][nt][1]);
                stsv2(sb + SM_EP + (uint32_t)(((row + 8) * EPW + col) * 4),
                      acc[mt][nt][2], acc[mt][nt][3]);
            }
        }
        if (t < No) {
            float act = aact[o_base + t];
            float thv = athr[o_base + t];
            float s = 0.0f;
            #pragma unroll 8
            for (int b = 0; b < Bb; b++) {
                float a = 1.0f / (1.0f + expf(-g_ctx_mean[b] * act));
                s += (a > thv) ? a : 0.0f;
            }
            maf[t] = s * (1.0f / Bb);
        }
        barsync(5, 128);

        {
            const int ol = t & 7;
            const int bg = t >> 3;          // 0..15
            const int oo = o_base + ol;
            const float ma = maf[ol];
            const float bv = bias[oo];
            float sg[Ss];
            #pragma unroll
            for (int s = 0; s < Ss; s++) sg[s] = sigmoidf_(gates[oo * Ss + s]);
            #pragma unroll
            for (int j = 0; j < 4; j++) {
                int b = bg * 4 + j;
                const float* e = epf + b * EPW + ol * NCOL;
                float v = fmaf(e[10], ma, bv);
                #pragma unroll
                for (int s = 0; s < Ss; s++)
                    v = fmaf(sg[s], fmaxf(e[s], 0.0f), v);
                out[(size_t)b * Oo + oo] = fmaxf(v, 0.0f);
            }
        }
    } else {
        // ================= PRODUCER (4 warps) =================
        const int p = t - 128;           // 0..127
        const int o_loc = p >> 4;        // 0..7
        const int q = p & 15;            // k-quarter: k = 4q..4q+3
        const int o = o_base + o_loc;
        const int nrow = o_loc * NCOL;
        const float thr = pthr[0];
        const float* dsrc = dend + ((size_t)o * Ii + 4 * q) * Ss;
        const float* wsrc = weight + (size_t)o * Ii + 4 * q;
        const float* csrc = cstr + (size_t)o * Ii + 4 * q;

        for (int c = 0; c < NCHUNKS; c++) {
            const int st = c & (STAGES - 1);
            const int kb = c * KCH;
            if (c >= STAGES)
                mbar_wait(EMPTYB + st * 8, ((c - STAGES) >> 2) & 1);

            // A tile: x fp16, 512 x 16B over 128 threads
            #pragma unroll
            for (int r = 0; r < 4; r++) {
                int g = p + 128 * r;              // 0..511
                int b = g >> 3, sg_ = g & 7;
                const char* src = reinterpret_cast<const char*>(g_xh)
                                + ((size_t)b * Ii + kb + sg_ * 8) * 2;
                cpa16(aT0 + st * A_TILE + swz((uint32_t)b * 128 + sg_ * 16), src);
            }
            cpa_commit();

            // one (o, 4k) cell: 12 independent LDG.128
            float4 d4[10];
            const float4* dp4 = reinterpret_cast<const float4*>(dsrc + (size_t)kb * Ss);
            #pragma unroll
            for (int j = 0; j < 10; j++) d4[j] = dp4[j];
            float4 w4 = *reinterpret_cast<const float4*>(wsrc + kb);
            float4 c4 = *reinterpret_cast<const float4*>(csrc + kb);

            float f[40];
            #pragma unroll
            for (int j = 0; j < 10; j++) {
                f[4*j] = d4[j].x; f[4*j+1] = d4[j].y;
                f[4*j+2] = d4[j].z; f[4*j+3] = d4[j].w;
            }
            float wv[4];
            wv[0] = (fabsf(w4.x) * c4.x > thr) ? w4.x : 0.0f;
            wv[1] = (fabsf(w4.y) * c4.y > thr) ? w4.y : 0.0f;
            wv[2] = (fabsf(w4.z) * c4.z > thr) ? w4.z : 0.0f;
            wv[3] = (fabsf(w4.w) * c4.w > thr) ? w4.w : 0.0f;

            const uint32_t bb = bT0 + st * B_TILE;
            #pragma unroll
            for (int s = 0; s < 11; s++) {
                float a0, a1, a2, a3;
                if (s < 10) { a0 = f[s]; a1 = f[10+s]; a2 = f[20+s]; a3 = f[30+s]; }
                else        { a0 = wv[0]; a1 = wv[1]; a2 = wv[2]; a3 = wv[3]; }
                uint32_t h0 = cvt_f16x2(a1, a0);
                uint32_t h1 = cvt_f16x2(a3, a2);
                sts64(bb + swz((uint32_t)(nrow + s) * 128 + q * 8), h0, h1);
            }

            cpa_waitg0();
            __syncwarp();
            if (lane == 0) mbar_arrive(FULLB + st * 8);
        }
    }
}

extern "C" void kernel_launch(void* const* d_in, const int* in_sizes, int n_in,
                              void* d_out, int out_size) {
    const float* x      = (const float*)d_in[0];
    const float* ctx    = (const float*)d_in[1];
    const float* weight = (const float*)d_in[3];
    const float* bias   = (const float*)d_in[4];
    const float* aact   = (const float*)d_in[5];
    const float* athr   = (const float*)d_in[6];
    const float* dend   = (const float*)d_in[7];
    const float* gates  = (const float*)d_in[8];
    const float* cstr   = (const float*)d_in[9];
    const float* pthr   = (const float*)d_in[10];
    float* out = (float*)d_out;

    cudaFuncSetAttribute(k_main, cudaFuncAttributeMaxDynamicSharedMemorySize, SMEM_REQ);

    k_prep<<<Bb, 256>>>(ctx, x);
    k_main<<<Oo / No, NTHREADS, SMEM_REQ>>>(dend, weight, cstr, pthr, gates, bias,
                                            aact, athr, out);
}